// round 14
// baseline (speedup 1.0000x reference)
#include <cuda_runtime.h>
#include <cuda_fp16.h>
#include <math.h>
#include <stdint.h>

// ---------------- constants ----------------
#define GT_OFF 19267584      // 16*3136*384

// ---------------- scratch (device globals; allocation-free) ----------------
__device__ __half h_ln1[19267584];     // dwconv+LN out; later reused as xlocal fp16
__device__ __half h_h1[77070336];      // MLP hidden
__device__ __half h_pool1[4816896];    // down_1 fp16 (implicit-conv A operand)
__device__ __half h_xd[1204224];       // downsampled tokens
__device__ __half h_xds[1204224];      // global-agg MHA out
__device__ __half h_gtok[301056];      // global_token fp16
__device__ __half h_gt[301056];        // updated global token fp16
__device__ __half h_x[19267584];       // x fp16
__device__ __half h_qx[19267584];      // q for global broadcast (fp16)
__device__ __half h_xsum[19267584];    // xlocal + xglobal
__device__ float g_c2pre[4816896];     // conv2 pre-LN
__device__ float g_qkv[3612672];       // [B,196,1152]
__device__ float g_kv2[2408448];       // [B,196,768]
__device__ float g_qg[301056];         // [B,49,384]
__device__ float g_kv3[602112];        // [B,49,768]
__device__ __half w_pw1T[589824];
__device__ __half w_pw2T[589824];
__device__ __half w_qkvT[442368];
__device__ __half w_ugkvT[294912];
__device__ __half w_ugqT[147456];
__device__ __half w_gbkvT[294912];
__device__ __half w_gbqT[147456];
__device__ __half w_projT[147456];
__device__ __half w_convT[1327104];

// ---------------- helpers ----------------
__device__ __forceinline__ float gelu_exact(float x){
    return 0.5f * x * (1.0f + erff(x * 0.70710678118654752f));
}
__device__ __forceinline__ uint32_t smem_u32(const void* p) {
    uint32_t a;
    asm("{ .reg .u64 t; cvta.to.shared.u64 t, %1; cvt.u32.u64 %0, t; }" : "=r"(a) : "l"(p));
    return a;
}
__device__ __forceinline__ void mma16(float* d, const unsigned* a, const unsigned* b){
    asm volatile("mma.sync.aligned.m16n8k16.row.col.f32.f16.f16.f32 "
        "{%0,%1,%2,%3},{%4,%5,%6,%7},{%8,%9},{%0,%1,%2,%3};"
        : "+f"(d[0]), "+f"(d[1]), "+f"(d[2]), "+f"(d[3])
        : "r"(a[0]), "r"(a[1]), "r"(a[2]), "r"(a[3]), "r"(b[0]), "r"(b[1]));
}
__device__ __forceinline__ void ldsm4(unsigned& r0, unsigned& r1, unsigned& r2, unsigned& r3,
                                      uint32_t addr){
    asm volatile("ldmatrix.sync.aligned.m8n8.x4.shared.b16 {%0,%1,%2,%3}, [%4];"
        : "=r"(r0), "=r"(r1), "=r"(r2), "=r"(r3) : "r"(addr));
}
__device__ __forceinline__ void cp16(uint32_t s, const void* g) {
    asm volatile("cp.async.cg.shared.global [%0], [%1], 16;" :: "r"(s), "l"(g));
}
__device__ __forceinline__ void cp16z(uint32_t s, const void* g, int sz) {
    asm volatile("cp.async.cg.shared.global [%0], [%1], 16, %2;" :: "r"(s), "l"(g), "r"(sz));
}
#define CP_COMMIT() asm volatile("cp.async.commit_group;" ::: "memory")
#define CP_WAIT(n)  asm volatile("cp.async.wait_group %0;" :: "n"(n) : "memory")

// A-operand staging: dense (CONV=0) or implicit 3x3 SAME conv over [16,28,28,384] (CONV=1)
template<int CONV>
__device__ __forceinline__ void stageA(uint32_t dst, const __half* __restrict__ Abase,
                                       int K, int r, int c, int ko, bool rowok,
                                       int b, int h, int w)
{
    if (!CONV) {
        if (rowok) cp16(dst, Abase + (size_t)r * K + ko + c * 8);
    } else {
        int k = ko + c * 8;
        int kk = k / 384;            // tap index 0..8
        int cin = k - kk * 384;      // channel (8-aligned)
        int ky = kk / 3, kx = kk - 3 * ky;
        int hh = h + ky - 1, ww = w + kx - 1;
        bool inb = ((unsigned)hh < 28u) && ((unsigned)ww < 28u);
        const __half* src = inb
            ? Abase + (((size_t)(b * 28 + hh) * 28 + ww) * 384 + cin)
            : Abase;
        cp16z(dst, src, inb ? 16 : 0);
    }
}

// ---------------- FP16 GEMM: mma.m16n8k16 + ldmatrix + cp.async 3-stage ring (K32) -------
// CTA tile 64x128, 128 threads (4 warps x 64x32) -> 4 CTAs/SM for latency hiding.
// smem stage: A 64x40h (5120 B) + B 128x40h (10240 B); 3 stages = 46080 B.
// MODE 0: C = A@B ; 1: +bias ; 2: gelu(+bias) ; 3: (+bias)*gamma + res
template<int MODE, int CONV>
__global__ void __launch_bounds__(128, 4) hgemm(
    const __half* __restrict__ A, const __half* __restrict__ BT,
    const float* __restrict__ bias, const float* __restrict__ gamma,
    const float* __restrict__ res,
    float* __restrict__ Cf, __half* __restrict__ Ch,
    int M, int N, int K)
{
    extern __shared__ __half smh[];
    const uint32_t AsmU = smem_u32(smh);        // 3 x 5120 B
    const uint32_t BsmU = AsmU + 15360;         // 3 x 10240 B

    const int tid  = threadIdx.x;
    const int warp = tid >> 5, lane = tid & 31;
    const int wn = warp * 32;
    const int bm = blockIdx.y * 64;
    const int bn = blockIdx.x * 128;

    float acc[4][4][4];
    #pragma unroll
    for (int t = 0; t < 4; t++)
        #pragma unroll
        for (int u = 0; u < 4; u++)
            #pragma unroll
            for (int e = 0; e < 4; e++) acc[t][u][e] = 0.f;

    const int maxrowA = M - bm;
    const __half* Abase = CONV ? A : (A + (size_t)bm * K);
    const __half* Bbase = BT + (size_t)bn * K;

    // staging per thread: A chunks 2*tid, 2*tid+1 (row tid>>1); B row tid, all 4 chunks
    const int ra = tid >> 1;
    const int ca0 = (tid & 1) * 2, ca1 = ca0 + 1;
    const bool okA = ra < maxrowA;
    int bb = 0, hh0 = 0, ww0 = 0;
    if (CONV) {
        int p0 = bm + ra; bb = p0 / 784; int q0 = p0 - bb * 784; hh0 = q0 / 28; ww0 = q0 - hh0 * 28;
    }
    const uint32_t aoffr = (uint32_t)ra * 80;
    const uint32_t boffr = (uint32_t)tid * 80;
    const __half* Brow = Bbase + (size_t)tid * K;

    const int a_row = lane & 15;
    const int a_kc  = (lane >> 4) & 1;
    const int b_row = (lane & 7) | ((lane >> 1) & 8);
    const int b_kc  = (lane >> 3) & 1;

    const int T = K >> 5;

    // prologue: stage chunks 0 (+1)
    {
        stageA<CONV>(AsmU + aoffr + ca0 * 16, Abase, K, ra, ca0, 0, okA, bb, hh0, ww0);
        stageA<CONV>(AsmU + aoffr + ca1 * 16, Abase, K, ra, ca1, 0, okA, bb, hh0, ww0);
        #pragma unroll
        for (int i = 0; i < 4; i++) cp16(BsmU + boffr + i * 16, Brow + i * 8);
        CP_COMMIT();
        if (T > 1) {
            stageA<CONV>(AsmU + 5120 + aoffr + ca0 * 16, Abase, K, ra, ca0, 32, okA, bb, hh0, ww0);
            stageA<CONV>(AsmU + 5120 + aoffr + ca1 * 16, Abase, K, ra, ca1, 32, okA, bb, hh0, ww0);
            #pragma unroll
            for (int i = 0; i < 4; i++) cp16(BsmU + 10240 + boffr + i * 16, Brow + 32 + i * 8);
            CP_COMMIT();
        }
    }

    int buf = 0, nbuf = (T > 2) ? 2 : (T == 2 ? 0 : 1);
    for (int it = 0; it < T; ++it) {
        if (it + 1 < T) CP_WAIT(1); else CP_WAIT(0);
        __syncthreads();
        if (it + 2 < T) {
            const int ko = (it + 2) << 5;
            stageA<CONV>(AsmU + (uint32_t)nbuf * 5120 + aoffr + ca0 * 16, Abase, K, ra, ca0, ko, okA, bb, hh0, ww0);
            stageA<CONV>(AsmU + (uint32_t)nbuf * 5120 + aoffr + ca1 * 16, Abase, K, ra, ca1, ko, okA, bb, hh0, ww0);
            #pragma unroll
            for (int i = 0; i < 4; i++)
                cp16(BsmU + (uint32_t)nbuf * 10240 + boffr + i * 16, Brow + ko + i * 8);
            CP_COMMIT();
        }
        const uint32_t Abuf = AsmU + (uint32_t)buf * 5120;
        const uint32_t Bbuf = BsmU + (uint32_t)buf * 10240;
        #pragma unroll
        for (int ks = 0; ks < 2; ks++) {
            unsigned af[4][4], bf[4][2];
            #pragma unroll
            for (int t = 0; t < 4; t++) {
                const uint32_t addr = Abuf + (uint32_t)(t * 16 + a_row) * 80
                                    + (uint32_t)(ks * 16 + a_kc * 8) * 2;
                ldsm4(af[t][0], af[t][1], af[t][2], af[t][3], addr);
            }
            #pragma unroll
            for (int u2 = 0; u2 < 2; u2++) {
                const uint32_t addr = Bbuf + (uint32_t)(wn + u2 * 16 + b_row) * 80
                                    + (uint32_t)(ks * 16 + b_kc * 8) * 2;
                ldsm4(bf[2 * u2][0], bf[2 * u2][1], bf[2 * u2 + 1][0], bf[2 * u2 + 1][1], addr);
            }
            #pragma unroll
            for (int t = 0; t < 4; t++)
                #pragma unroll
                for (int u = 0; u < 4; u++)
                    mma16(acc[t][u], af[t], bf[u]);
        }
        buf = (buf == 2) ? 0 : buf + 1;
        nbuf = (nbuf == 2) ? 0 : nbuf + 1;
    }

    // ---- epilogue ----
    #pragma unroll
    for (int t = 0; t < 4; t++) {
        const int row0 = bm + t * 16 + (lane >> 2);
        #pragma unroll
        for (int u = 0; u < 4; u++) {
            const int col = bn + wn + u * 8 + ((lane & 3) << 1);
            float b0f = 0.f, b1f = 0.f;
            if (MODE >= 1) { b0f = bias[col]; b1f = bias[col + 1]; }
            #pragma unroll
            for (int h = 0; h < 2; h++) {
                const int row = row0 + h * 8;
                if (row >= M) continue;
                float v0 = acc[t][u][h * 2 + 0] + b0f;
                float v1 = acc[t][u][h * 2 + 1] + b1f;
                if (MODE == 2) { v0 = gelu_exact(v0); v1 = gelu_exact(v1); }
                if (MODE == 3) {
                    const float* rr = res + (size_t)row * N + col;
                    v0 = v0 * gamma[col]     + rr[0];
                    v1 = v1 * gamma[col + 1] + rr[1];
                }
                if (Cf) *(float2*)&Cf[(size_t)row * N + col] = make_float2(v0, v1);
                if (Ch) *(__half2*)&Ch[(size_t)row * N + col] = __floats2half2_rn(v0, v1);
            }
        }
    }
}

// ---------------- fused weight prep: all transposes + f2h in ONE kernel ----------------
__global__ void prep_weights_kernel(
    const float* __restrict__ pw1, const float* __restrict__ pw2,
    const float* __restrict__ qkv, const float* __restrict__ ugkv,
    const float* __restrict__ ugq, const float* __restrict__ gbkv,
    const float* __restrict__ gbq, const float* __restrict__ proj,
    const float* __restrict__ convw, const float* __restrict__ gtok,
    __half* __restrict__ pw1T, __half* __restrict__ pw2T,
    __half* __restrict__ qkvT, __half* __restrict__ ugkvT,
    __half* __restrict__ ugqT, __half* __restrict__ gbkvT,
    __half* __restrict__ gbqT, __half* __restrict__ projT,
    __half* __restrict__ convT, __half* __restrict__ gtokh)
{
    int idx = blockIdx.x * blockDim.x + threadIdx.x;
    if (idx < 589824) {
        int n = idx / 384, k = idx % 384;
        pw1T[idx] = __float2half(pw1[(size_t)k * 1536 + n]); return;
    }
    idx -= 589824;
    if (idx < 589824) {
        int n = idx / 1536, k = idx % 1536;
        pw2T[idx] = __float2half(pw2[(size_t)k * 384 + n]); return;
    }
    idx -= 589824;
    if (idx < 442368) {
        int n = idx / 384, k = idx % 384;
        qkvT[idx] = __float2half(qkv[(size_t)k * 1152 + n]); return;
    }
    idx -= 442368;
    if (idx < 294912) {
        int n = idx / 384, k = idx % 384;
        ugkvT[idx] = __float2half(ugkv[(size_t)k * 768 + n]); return;
    }
    idx -= 294912;
    if (idx < 147456) {
        int n = idx / 384, k = idx % 384;
        ugqT[idx] = __float2half(ugq[(size_t)k * 384 + n]); return;
    }
    idx -= 147456;
    if (idx < 294912) {
        int n = idx / 384, k = idx % 384;
        gbkvT[idx] = __float2half(gbkv[(size_t)k * 768 + n]); return;
    }
    idx -= 294912;
    if (idx < 147456) {
        int n = idx / 384, k = idx % 384;
        gbqT[idx] = __float2half(gbq[(size_t)k * 384 + n]); return;
    }
    idx -= 147456;
    if (idx < 147456) {
        int n = idx / 384, k = idx % 384;
        projT[idx] = __float2half(proj[(size_t)k * 384 + n]); return;
    }
    idx -= 147456;
    if (idx < 1327104) {
        int o = idx / 3456, j = idx % 3456;
        int kk = j / 384, i = j % 384;
        convT[idx] = __float2half(convw[(size_t)o * 3456 + i * 9 + kk]); return;
    }
    idx -= 1327104;
    if (idx < 301056) {
        gtokh[idx] = __float2half(gtok[idx]);
    }
}
#define PREP_TOTAL 4282368

// ---------------- dwconv 3x3 depthwise + LN(1e-6) -> fp16; also emits x as fp16 ----------
__global__ void dwconv_ln_kernel(const float* __restrict__ x,
                                 const float* __restrict__ dw, const float* __restrict__ db,
                                 const float* __restrict__ gam, const float* __restrict__ bet,
                                 __half* __restrict__ out, __half* __restrict__ xh)
{
    __shared__ float sred[64];
    const int pix = blockIdx.x;
    const int b = pix / 3136, hw = pix % 3136;
    const int h = hw / 56, w = hw % 56;
    const int tid = threadIdx.x;
    float v[3];
    float s = 0.f, s2 = 0.f;
    #pragma unroll
    for (int r = 0; r < 3; r++) {
        int c = tid + r * 128;
        float acc = db[c];
        float ctr = 0.f;
        #pragma unroll
        for (int ky = 0; ky < 3; ky++) {
            int hh = h + ky - 1;
            if ((unsigned)hh >= 56u) continue;
            #pragma unroll
            for (int kx = 0; kx < 3; kx++) {
                int ww = w + kx - 1;
                if ((unsigned)ww >= 56u) continue;
                float xv = x[((size_t)b * 3136 + hh * 56 + ww) * 384 + c];
                if (ky == 1 && kx == 1) ctr = xv;
                acc = fmaf(xv, dw[c * 9 + ky * 3 + kx], acc);
            }
        }
        xh[(size_t)pix * 384 + c] = __float2half(ctr);
        v[r] = acc; s += acc; s2 = fmaf(acc, acc, s2);
    }
    int lane = tid & 31, warp = tid >> 5;
    #pragma unroll
    for (int off = 16; off; off >>= 1) {
        s  += __shfl_xor_sync(0xffffffffu, s, off);
        s2 += __shfl_xor_sync(0xffffffffu, s2, off);
    }
    if (lane == 0) { sred[warp] = s; sred[warp + 32] = s2; }
    __syncthreads();
    if (warp == 0) {
        float a  = (lane < 4) ? sred[lane] : 0.f;
        float b2 = (lane < 4) ? sred[lane + 32] : 0.f;
        #pragma unroll
        for (int off = 2; off; off >>= 1) {
            a  += __shfl_xor_sync(0xffffffffu, a, off);
            b2 += __shfl_xor_sync(0xffffffffu, b2, off);
        }
        if (lane == 0) { sred[0] = a; sred[1] = b2; }
    }
    __syncthreads();
    float mean = sred[0] * (1.f / 384.f);
    float var  = sred[1] * (1.f / 384.f) - mean * mean;
    float rstd = rsqrtf(var + 1e-6f);
    #pragma unroll
    for (int r = 0; r < 3; r++) {
        int c = tid + r * 128;
        out[(size_t)pix * 384 + c] = __float2half((v[r] - mean) * rstd * gam[c] + bet[c]);
    }
}

// ---------------- fused LN(1e-5)+ReLU+AvgPool2(2,2): [16,28,28,384]f32 -> [16,14,14,384]f16
__global__ void ln_relu_pool_kernel(const float* __restrict__ in,
                                    const float* __restrict__ gam, const float* __restrict__ bet,
                                    __half* __restrict__ out)
{
    __shared__ float sred[4][4][2];
    const int opix = blockIdx.x;
    const int b = opix / 196, q = opix % 196;
    const int ho = q / 14, wo = q % 14;
    const int tid = threadIdx.x;
    const int lane = tid & 31, warp = tid >> 5;

    size_t ibase[4];
    #pragma unroll
    for (int pp = 0; pp < 4; pp++) {
        int hi = 2 * ho + (pp >> 1), wi = 2 * wo + (pp & 1);
        ibase[pp] = (((size_t)b * 28 + hi) * 28 + wi) * 384;
    }
    float v[4][3];
    float s[4] = {0.f, 0.f, 0.f, 0.f}, s2[4] = {0.f, 0.f, 0.f, 0.f};
    #pragma unroll
    for (int pp = 0; pp < 4; pp++) {
        #pragma unroll
        for (int r = 0; r < 3; r++) {
            float a = in[ibase[pp] + tid + r * 128];
            v[pp][r] = a; s[pp] += a; s2[pp] = fmaf(a, a, s2[pp]);
        }
    }
    #pragma unroll
    for (int pp = 0; pp < 4; pp++) {
        float a = s[pp], c = s2[pp];
        #pragma unroll
        for (int off = 16; off; off >>= 1) {
            a += __shfl_xor_sync(0xffffffffu, a, off);
            c += __shfl_xor_sync(0xffffffffu, c, off);
        }
        if (lane == 0) { sred[warp][pp][0] = a; sred[warp][pp][1] = c; }
    }
    __syncthreads();
    float mean[4], rstd[4];
    #pragma unroll
    for (int pp = 0; pp < 4; pp++) {
        float a = sred[0][pp][0] + sred[1][pp][0] + sred[2][pp][0] + sred[3][pp][0];
        float c = sred[0][pp][1] + sred[1][pp][1] + sred[2][pp][1] + sred[3][pp][1];
        float m = a * (1.f / 384.f);
        mean[pp] = m;
        rstd[pp] = rsqrtf(c * (1.f / 384.f) - m * m + 1e-5f);
    }
    #pragma unroll
    for (int r = 0; r < 3; r++) {
        int c = tid + r * 128;
        float g = gam[c], be = bet[c];
        float acc = 0.f;
        #pragma unroll
        for (int pp = 0; pp < 4; pp++) {
            float val = (v[pp][r] - mean[pp]) * rstd[pp] * g + be;
            acc += fmaxf(val, 0.f);
        }
        out[(size_t)opix * 384 + c] = __float2half(0.25f * acc);
    }
}

// ---------------- AvgPool2d(2,2) NHWC fp16 -> fp16 (half2-vectorized) ----------------
__global__ void avgpool2h_kernel(const __half* __restrict__ in, __half* __restrict__ out,
                                 int B_, int Ho, int Wo)
{
    int idx = blockIdx.x * blockDim.x + threadIdx.x;
    int total = B_ * Ho * Wo * 192;
    if (idx >= total) return;
    int c2 = idx % 192; int t = idx / 192;
    int wo = t % Wo; t /= Wo;
    int ho = t % Ho; int b = t / Ho;
    int Hi = Ho * 2, Wi = Wo * 2;
    const __half2* p = (const __half2*)(in + (((size_t)b * Hi + 2 * ho) * Wi + 2 * wo) * 384) + c2;
    const size_t rs = (size_t)Wi * 192;
    float2 a0 = __half22float2(p[0]);
    float2 a1 = __half22float2(p[192]);
    float2 a2 = __half22float2(p[rs]);
    float2 a3 = __half22float2(p[rs + 192]);
    ((__half2*)out)[idx] = __floats2half2_rn(0.25f * (a0.x + a1.x + a2.x + a3.x),
                                             0.25f * (a0.y + a1.y + a2.y + a3.y));
}

// ---------------- MHA v2: warp per query-PAIR; lane-per-key scores ----------------
__global__ void mha_kernel(const float* __restrict__ q, const __half* __restrict__ qh, int qs,
                           const float* __restrict__ k, int ks,
                           const float* __restrict__ v, int vs,
                           float* __restrict__ of, __half* __restrict__ oh, int os,
                           int Nq, int Nk, const __half* __restrict__ addsrc)
{
    extern __shared__ float sm[];
    float2* ksh2 = (float2*)sm;
    float2* vsh2 = ksh2 + (size_t)Nk * 32;
    const int nw = blockDim.x >> 5;
    float2* qbase = vsh2 + (size_t)Nk * 32;
    float*  scbase = (float*)(qbase + nw * 64);

    const int bh = blockIdx.x;
    const int b = bh / 6, h = bh % 6;
    const int tid = threadIdx.x;
    const int warp = tid >> 5, lane = tid & 31;

    const float* kb = k + (size_t)b * Nk * ks + h * 64;
    const float* vb = v + (size_t)b * Nk * vs + h * 64;
    for (int idx = tid; idx < Nk * 32; idx += blockDim.x) {
        int j = idx >> 5, d2 = idx & 31;
        ksh2[idx] = *(const float2*)(kb + (size_t)j * ks + 2 * d2);
        vsh2[idx] = *(const float2*)(vb + (size_t)j * vs + 2 * d2);
    }
    __syncthreads();

    float2* qa2 = qbase + warp * 64;
    float2* qb2 = qa2 + 32;
    float* sca = scbase + warp * 2 * Nk;
    float* scb = sca + Nk;

    const int npairs = (Nq + 1) >> 1;
    for (int qp = blockIdx.y * nw + warp; qp < npairs; qp += gridDim.y * nw) {
        const int qia = 2 * qp;
        const int qib = qia + 1;
        const bool hasb = qib < Nq;
        const int qibc = hasb ? qib : qia;
        {
            float a0, a1, b0, b1;
            if (qh) {
                __half2 ha = *(const __half2*)(qh + ((size_t)b * Nq + qia) * qs + h * 64 + 2 * lane);
                __half2 hb = *(const __half2*)(qh + ((size_t)b * Nq + qibc) * qs + h * 64 + 2 * lane);
                float2 fa = __half22float2(ha), fb = __half22float2(hb);
                a0 = fa.x; a1 = fa.y; b0 = fb.x; b1 = fb.y;
            } else {
                float2 fa = *(const float2*)(q + ((size_t)b * Nq + qia) * qs + h * 64 + 2 * lane);
                float2 fb = *(const float2*)(q + ((size_t)b * Nq + qibc) * qs + h * 64 + 2 * lane);
                a0 = fa.x; a1 = fa.y; b0 = fb.x; b1 = fb.y;
            }
            qa2[lane] = make_float2(a0 * 0.125f, a1 * 0.125f);
            qb2[lane] = make_float2(b0 * 0.125f, b1 * 0.125f);
        }
        __syncwarp();

        float ma = -1e30f, mb = -1e30f;
        for (int j0 = 0; j0 < Nk; j0 += 32) {
            const int j = j0 + lane;
            const float2* kj = ksh2 + (size_t)j * 32;
            float sa0 = 0.f, sa1 = 0.f, sb0 = 0.f, sb1 = 0.f;
            int d2 = lane;
            #pragma unroll 8
            for (int dd = 0; dd < 32; dd += 2) {
                float2 k2 = kj[d2];
                float2 qa = qa2[d2];
                float2 qb = qb2[d2];
                sa0 = fmaf(k2.x, qa.x, fmaf(k2.y, qa.y, sa0));
                sb0 = fmaf(k2.x, qb.x, fmaf(k2.y, qb.y, sb0));
                int d2b = (d2 + 1) & 31;
                float2 k3 = kj[d2b];
                float2 qa3 = qa2[d2b];
                float2 qb3 = qb2[d2b];
                sa1 = fmaf(k3.x, qa3.x, fmaf(k3.y, qa3.y, sa1));
                sb1 = fmaf(k3.x, qb3.x, fmaf(k3.y, qb3.y, sb1));
                d2 = (d2 + 2) & 31;
            }
            float sa = sa0 + sa1, sb = sb0 + sb1;
            if (j < Nk) {
                sca[j] = sa; scb[j] = sb;
                ma = fmaxf(ma, sa); mb = fmaxf(mb, sb);
            }
        }
        #pragma unroll
        for (int off = 16; off; off >>= 1) {
            ma = fmaxf(ma, __shfl_xor_sync(0xffffffffu, ma, off));
            mb = fmaxf(mb, __shfl_xor_sync(0xffffffffu, mb, off));
        }
        float suma = 0.f, sumb = 0.f;
        for (int j = lane; j < Nk; j += 32) {
            float ea = expf(sca[j] - ma); sca[j] = ea; suma += ea;
            float eb = expf(scb[j] - mb); scb[j] = eb; sumb += eb;
        }
        #pragma unroll
        for (int off = 16; off; off >>= 1) {
            suma += __shfl_xor_sync(0xffffffffu, suma, off);
            sumb += __shfl_xor_sync(0xffffffffu, sumb, off);
        }
        const float inva = 1.f / suma, invb = 1.f / sumb;
        __syncwarp();

        float2 oa = make_float2(0.f, 0.f), ob = make_float2(0.f, 0.f);
        const float2* vrow = vsh2 + lane;
        for (int j = 0; j < Nk; j++) {
            float pa = sca[j], pb = scb[j];
            float2 v2 = vrow[(size_t)j * 32];
            oa.x = fmaf(pa, v2.x, oa.x); oa.y = fmaf(pa, v2.y, oa.y);
            ob.x = fmaf(pb, v2.x, ob.x); ob.y = fmaf(pb, v2.y, ob.y);
        }
        oa.x *= inva; oa.y *= inva; ob.x *= invb; ob.y *= invb;
        if (addsrc) {
            float2 ra = __half22float2(*(const __half2*)(addsrc + ((size_t)b * Nq + qia) * 384 + h * 64 + 2 * lane));
            oa.x += ra.x; oa.y += ra.y;
            if (hasb) {
                float2 rb = __half22float2(*(const __half2*)(addsrc + ((size_t)b * Nq + qib) * 384 + h * 64 + 2 * lane));
                ob.x += rb.x; ob.y += rb.y;
            }
        }
        const size_t oba = ((size_t)b * Nq + qia) * os + h * 64 + 2 * lane;
        if (of) {
            *(float2*)&of[oba] = oa;
            if (hasb) *(float2*)&of[oba + os] = ob;
        }
        if (oh) {
            *(__half2*)&oh[oba] = __floats2half2_rn(oa.x, oa.y);
            if (hasb) *(__half2*)&oh[oba + os] = __floats2half2_rn(ob.x, ob.y);
        }
        __syncwarp();
    }
}

// ---------------- launch ----------------
extern "C" void kernel_launch(void* const* d_in, const int* in_sizes, int n_in,
                              void* d_out, int out_size)
{
    const float* x        = (const float*)d_in[0];
    const float* gtok     = (const float*)d_in[1];
    const float* we_dw_w  = (const float*)d_in[2];
    const float* we_dw_b  = (const float*)d_in[3];
    const float* we_ln_g  = (const float*)d_in[4];
    const float* we_ln_b  = (const float*)d_in[5];
    const float* we_pw1_w = (const float*)d_in[6];
    const float* we_pw1_b = (const float*)d_in[7];
    const float* we_pw2_w = (const float*)d_in[8];
    const float* we_pw2_b = (const float*)d_in[9];
    const float* we_gamma = (const float*)d_in[10];
    const float* cb_conv_w= (const float*)d_in[11];
    const float* cb_ln_g  = (const float*)d_in[12];
    const float* cb_ln_b  = (const float*)d_in[13];
    const float* ga_qkv_w = (const float*)d_in[14];
    const float* ug_kv_w  = (const float*)d_in[15];
    const float* ug_q_w   = (const float*)d_in[16];
    const float* gb_kv_w  = (const float*)d_in[17];
    const float* gb_q_w   = (const float*)d_in[18];
    const float* proj_w   = (const float*)d_in[19];
    const float* proj_b   = (const float*)d_in[20];

    float* out = (float*)d_out;
    float* gt_out = out + GT_OFF;

    __half *ln1h, *h1h, *pool1h, *xdh, *xdsh, *gtokh, *gth, *xh, *qxh, *xsumh;
    __half *pw1T, *pw2T, *qkvT, *ugkvT, *ugqT, *gbkvT, *gbqT, *projT, *convT;
    float *c2pre, *qkv, *kv2, *qg, *kv3;
    cudaGetSymbolAddress((void**)&ln1h,   h_ln1);
    cudaGetSymbolAddress((void**)&h1h,    h_h1);
    cudaGetSymbolAddress((void**)&pool1h, h_pool1);
    cudaGetSymbolAddress((void**)&xdh,    h_xd);
    cudaGetSymbolAddress((void**)&xdsh,   h_xds);
    cudaGetSymbolAddress((void**)&gtokh,  h_gtok);
    cudaGetSymbolAddress((void**)&gth,    h_gt);
    cudaGetSymbolAddress((void**)&xh,     h_x);
    cudaGetSymbolAddress((void**)&qxh,    h_qx);
    cudaGetSymbolAddress((void**)&xsumh,  h_xsum);
    cudaGetSymbolAddress((void**)&c2pre,  g_c2pre);
    cudaGetSymbolAddress((void**)&qkv,    g_qkv);
    cudaGetSymbolAddress((void**)&kv2,    g_kv2);
    cudaGetSymbolAddress((void**)&qg,     g_qg);
    cudaGetSymbolAddress((void**)&kv3,    g_kv3);
    cudaGetSymbolAddress((void**)&pw1T,   w_pw1T);
    cudaGetSymbolAddress((void**)&pw2T,   w_pw2T);
    cudaGetSymbolAddress((void**)&qkvT,   w_qkvT);
    cudaGetSymbolAddress((void**)&ugkvT,  w_ugkvT);
    cudaGetSymbolAddress((void**)&ugqT,   w_ugqT);
    cudaGetSymbolAddress((void**)&gbkvT,  w_gbkvT);
    cudaGetSymbolAddress((void**)&gbqT,   w_gbqT);
    cudaGetSymbolAddress((void**)&projT,  w_projT);
    cudaGetSymbolAddress((void**)&convT,  w_convT);
    __half* xlocalh = ln1h;   // reuse: ln1h is dead after MLP1

    const int SMEM_TG  = 46080;                        // 3*(5120+10240)
    const int SMEM196 = 2 * 196 * 256 + 4 * (512 + 8 * 196);   // 108672
    const int SMEM49  = 2 * 49  * 256 + 4 * (512 + 8 * 49);    // 28704
    cudaFuncSetAttribute(mha_kernel, cudaFuncAttributeMaxDynamicSharedMemorySize, SMEM196);
    cudaFuncSetAttribute((hgemm<0,0>), cudaFuncAttributeMaxDynamicSharedMemorySize, SMEM_TG);
    cudaFuncSetAttribute((hgemm<1,0>), cudaFuncAttributeMaxDynamicSharedMemorySize, SMEM_TG);
    cudaFuncSetAttribute((hgemm<2,0>), cudaFuncAttributeMaxDynamicSharedMemorySize, SMEM_TG);
    cudaFuncSetAttribute((hgemm<3,0>), cudaFuncAttributeMaxDynamicSharedMemorySize, SMEM_TG);
    cudaFuncSetAttribute((hgemm<0,1>), cudaFuncAttributeMaxDynamicSharedMemorySize, SMEM_TG);

    // ---- fused weight prep (one launch) ----
    prep_weights_kernel<<<(PREP_TOTAL + 255) / 256, 256>>>(
        we_pw1_w, we_pw2_w, ga_qkv_w, ug_kv_w, ug_q_w, gb_kv_w, gb_q_w, proj_w,
        cb_conv_w, gtok,
        pw1T, pw2T, qkvT, ugkvT, ugqT, gbkvT, gbqT, projT, convT, gtokh);

    // ConvEncoder: dwconv + LN -> fp16 (also emits x fp16)
    dwconv_ln_kernel<<<50176, 128>>>(x, we_dw_w, we_dw_b, we_ln_g, we_ln_b, ln1h, xh);

    // MLP1: gelu(ln1 @ pw1 + b1) -> fp16 hidden
    hgemm<2,0><<<dim3(12, 784), 128, SMEM_TG>>>(ln1h, pw1T, we_pw1_b, nullptr, nullptr,
                                                nullptr, h1h, 50176, 1536, 384);
    // MLP2 + layer-scale + residual -> fp16 xlocal (reuses ln1h)
    hgemm<3,0><<<dim3(3, 784), 128, SMEM_TG>>>(h1h, pw2T, we_pw2_b, we_gamma, x,
                                               nullptr, xlocalh, 50176, 384, 1536);
    // down_1: 56->28 fp16->fp16
    avgpool2h_kernel<<<(2408448 + 255) / 256, 256>>>(xlocalh, pool1h, 16, 28, 28);

    // ConvBNReLU: implicit-GEMM conv (no im2col), then fused LN+ReLU+pool -> fp16 tokens
    hgemm<0,1><<<dim3(3, 196), 128, SMEM_TG>>>(pool1h, convT, nullptr, nullptr, nullptr,
                                               c2pre, nullptr, 12544, 384, 3456);
    ln_relu_pool_kernel<<<3136, 128>>>(c2pre, cb_ln_g, cb_ln_b, xdh);

    // global aggregation MHSA
    hgemm<0,0><<<dim3(9, 49), 128, SMEM_TG>>>(xdh, qkvT, nullptr, nullptr, nullptr,
                                              qkv, nullptr, 3136, 1152, 384);
    mha_kernel<<<dim3(96, 8), 128, SMEM196>>>(qkv, nullptr, 1152, qkv + 384, 1152,
                                              qkv + 768, 1152,
                                              nullptr, xdsh, 384, 196, 196, nullptr);

    // global token update
    hgemm<0,0><<<dim3(6, 49), 128, SMEM_TG>>>(xdsh, ugkvT, nullptr, nullptr, nullptr,
                                              kv2, nullptr, 3136, 768, 384);
    hgemm<0,0><<<dim3(3, 13), 128, SMEM_TG>>>(gtokh, ugqT, nullptr, nullptr, nullptr,
                                              qg, nullptr, 784, 384, 384);
    mha_kernel<<<dim3(96, 2), 128, SMEM196>>>(qg, nullptr, 384, kv2, 768, kv2 + 384, 768,
                                              gt_out, gth, 384, 49, 196, nullptr);

    // global broadcast
    hgemm<0,0><<<dim3(6, 13), 128, SMEM_TG>>>(gth, gbkvT, nullptr, nullptr, nullptr,
                                              kv3, nullptr, 784, 768, 384);
    hgemm<0,0><<<dim3(3, 784), 128, SMEM_TG>>>(xh, gbqT, nullptr, nullptr, nullptr,
                                               nullptr, qxh, 50176, 384, 384);
    // x_global + x_local(fp16) fused into MHA output -> fp16 xsum
    mha_kernel<<<dim3(96, 64), 128, SMEM49>>>(nullptr, qxh, 384, kv3, 768, kv3 + 384, 768,
                                              nullptr, xsumh, 384, 3136, 49, xlocalh);

    // final projection: xsum @ proj_w + proj_b -> out
    hgemm<1,0><<<dim3(3, 784), 128, SMEM_TG>>>(xsumh, projT, proj_b, nullptr, nullptr,
                                               out, nullptr, 50176, 384, 384);
}

// round 15
// speedup vs baseline: 1.1971x; 1.1971x over previous
#include <cuda_runtime.h>
#include <cuda_fp16.h>
#include <math.h>
#include <stdint.h>

// ---------------- constants ----------------
#define GT_OFF 19267584      // 16*3136*384

// ---------------- scratch (device globals; allocation-free) ----------------
__device__ __half h_ln1[19267584];     // dwconv+LN out; later reused as xlocal fp16
__device__ __half h_h1[77070336];      // MLP hidden
__device__ __half h_pool1[4816896];    // down_1 fp16 (implicit-conv A operand)
__device__ __half h_xd[1204224];       // downsampled tokens
__device__ __half h_xds[1204224];      // global-agg MHA out
__device__ __half h_gtok[301056];      // global_token fp16
__device__ __half h_gt[301056];        // updated global token fp16
__device__ __half h_x[19267584];       // x fp16
__device__ __half h_qx[19267584];      // q for global broadcast (fp16)
__device__ __half h_xsum[19267584];    // xlocal + xglobal
__device__ __half h_qkv[3612672];      // [B,196,1152] fp16
__device__ __half h_kv2[2408448];      // [B,196,768] fp16
__device__ __half h_kv3[602112];       // [B,49,768] fp16
__device__ float g_c2pre[4816896];     // conv2 pre-LN
__device__ float g_qg[301056];         // [B,49,384]
__device__ __half w_pw1T[589824];
__device__ __half w_pw2T[589824];
__device__ __half w_qkvT[442368];
__device__ __half w_ugkvT[294912];
__device__ __half w_ugqT[147456];
__device__ __half w_gbkvT[294912];
__device__ __half w_gbqT[147456];
__device__ __half w_projT[147456];
__device__ __half w_convT[1327104];

// ---------------- helpers ----------------
__device__ __forceinline__ float gelu_exact(float x){
    return 0.5f * x * (1.0f + erff(x * 0.70710678118654752f));
}
__device__ __forceinline__ uint32_t smem_u32(const void* p) {
    uint32_t a;
    asm("{ .reg .u64 t; cvta.to.shared.u64 t, %1; cvt.u32.u64 %0, t; }" : "=r"(a) : "l"(p));
    return a;
}
__device__ __forceinline__ void mma16(float* d, const unsigned* a, const unsigned* b){
    asm volatile("mma.sync.aligned.m16n8k16.row.col.f32.f16.f16.f32 "
        "{%0,%1,%2,%3},{%4,%5,%6,%7},{%8,%9},{%0,%1,%2,%3};"
        : "+f"(d[0]), "+f"(d[1]), "+f"(d[2]), "+f"(d[3])
        : "r"(a[0]), "r"(a[1]), "r"(a[2]), "r"(a[3]), "r"(b[0]), "r"(b[1]));
}
__device__ __forceinline__ void ldsm4(unsigned& r0, unsigned& r1, unsigned& r2, unsigned& r3,
                                      uint32_t addr){
    asm volatile("ldmatrix.sync.aligned.m8n8.x4.shared.b16 {%0,%1,%2,%3}, [%4];"
        : "=r"(r0), "=r"(r1), "=r"(r2), "=r"(r3) : "r"(addr));
}
__device__ __forceinline__ void cp16(uint32_t s, const void* g) {
    asm volatile("cp.async.cg.shared.global [%0], [%1], 16;" :: "r"(s), "l"(g));
}
__device__ __forceinline__ void cp16z(uint32_t s, const void* g, int sz) {
    asm volatile("cp.async.cg.shared.global [%0], [%1], 16, %2;" :: "r"(s), "l"(g), "r"(sz));
}
#define CP_COMMIT() asm volatile("cp.async.commit_group;" ::: "memory")
#define CP_WAIT(n)  asm volatile("cp.async.wait_group %0;" :: "n"(n) : "memory")

// A-operand staging: dense (CONV=0) or implicit 3x3 SAME conv over [16,28,28,384] (CONV=1)
template<int CONV>
__device__ __forceinline__ void stageA(uint32_t dst, const __half* __restrict__ Abase,
                                       int K, int r, int c, int ko, bool rowok,
                                       int b, int h, int w)
{
    if (!CONV) {
        if (rowok) cp16(dst, Abase + (size_t)r * K + ko + c * 8);
    } else {
        int k = ko + c * 8;
        int kk = k / 384;            // tap index 0..8
        int cin = k - kk * 384;      // channel (8-aligned)
        int ky = kk / 3, kx = kk - 3 * ky;
        int hh = h + ky - 1, ww = w + kx - 1;
        bool inb = ((unsigned)hh < 28u) && ((unsigned)ww < 28u);
        const __half* src = inb
            ? Abase + (((size_t)(b * 28 + hh) * 28 + ww) * 384 + cin)
            : Abase;
        cp16z(dst, src, inb ? 16 : 0);
    }
}

// ---------------- FP16 GEMM: mma.m16n8k16 + ldmatrix + cp.async 3-stage ring (K32) -------
// CTA tile 128x128, 256 threads (8 warps x 64x32). smem 3 x (A 128x40h + B 128x40h) = 61440 B.
// MODE 0: C = A@B ; 1: +bias ; 2: gelu(+bias) ; 3: (+bias)*gamma + res
template<int MODE, int CONV>
__global__ void __launch_bounds__(256, 2) hgemm(
    const __half* __restrict__ A, const __half* __restrict__ BT,
    const float* __restrict__ bias, const float* __restrict__ gamma,
    const float* __restrict__ res,
    float* __restrict__ Cf, __half* __restrict__ Ch,
    int M, int N, int K)
{
    extern __shared__ __half smh[];
    __half* Asm = smh;              // [3][128][40]
    __half* Bsm = smh + 3 * 5120;   // [3][128][40]
    const uint32_t AsmU = smem_u32(Asm);
    const uint32_t BsmU = smem_u32(Bsm);

    const int tid  = threadIdx.x;
    const int warp = tid >> 5, lane = tid & 31;
    const int wm = (warp >> 2) * 64;
    const int wn = (warp & 3) * 32;
    const int bm = blockIdx.y * 128;
    const int bn = blockIdx.x * 128;

    float acc[4][4][4];
    #pragma unroll
    for (int t = 0; t < 4; t++)
        #pragma unroll
        for (int u = 0; u < 4; u++)
            #pragma unroll
            for (int e = 0; e < 4; e++) acc[t][u][e] = 0.f;

    const int maxrowA = M - bm;
    const __half* Abase = CONV ? A : (A + (size_t)bm * K);
    const __half* Bbase = BT + (size_t)bn * K;

    const int cid0 = tid * 2;
    const int r0 = cid0 >> 2,       c0 = (cid0 & 3);
    const int r1 = (cid0 + 1) >> 2, c1 = ((cid0 + 1) & 3);
    const bool ok0 = r0 < maxrowA, ok1 = r1 < maxrowA;
    int b0 = 0, h0 = 0, w0 = 0, b1 = 0, h1 = 0, w1 = 0;
    if (CONV) {
        int p0 = bm + r0; b0 = p0 / 784; int q0 = p0 - b0 * 784; h0 = q0 / 28; w0 = q0 - h0 * 28;
        int p1 = bm + r1; b1 = p1 / 784; int q1 = p1 - b1 * 784; h1 = q1 / 28; w1 = q1 - h1 * 28;
    }

    const int a_row = lane & 15;
    const int a_kc  = (lane >> 4) & 1;
    const int b_row = (lane & 7) | ((lane >> 1) & 8);
    const int b_kc  = (lane >> 3) & 1;

    const int T = K >> 5;

    // prologue
    {
        stageA<CONV>(AsmU + r0 * 80 + c0 * 16, Abase, K, r0, c0, 0, ok0, b0, h0, w0);
        stageA<CONV>(AsmU + r1 * 80 + c1 * 16, Abase, K, r1, c1, 0, ok1, b1, h1, w1);
        cp16(BsmU + r0 * 80 + c0 * 16, Bbase + (size_t)r0 * K + c0 * 8);
        cp16(BsmU + r1 * 80 + c1 * 16, Bbase + (size_t)r1 * K + c1 * 8);
        CP_COMMIT();
        if (T > 1) {
            stageA<CONV>(AsmU + 10240 + r0 * 80 + c0 * 16, Abase, K, r0, c0, 32, ok0, b0, h0, w0);
            stageA<CONV>(AsmU + 10240 + r1 * 80 + c1 * 16, Abase, K, r1, c1, 32, ok1, b1, h1, w1);
            cp16(BsmU + 10240 + r0 * 80 + c0 * 16, Bbase + (size_t)r0 * K + 32 + c0 * 8);
            cp16(BsmU + 10240 + r1 * 80 + c1 * 16, Bbase + (size_t)r1 * K + 32 + c1 * 8);
            CP_COMMIT();
        }
    }

    int buf = 0, nbuf = (T > 2) ? 2 : (T == 2 ? 0 : 1);
    for (int it = 0; it < T; ++it) {
        if (it + 1 < T) CP_WAIT(1); else CP_WAIT(0);
        __syncthreads();
        if (it + 2 < T) {
            const int ko = (it + 2) << 5;
            const uint32_t off = (uint32_t)nbuf * 10240;
            stageA<CONV>(AsmU + off + r0 * 80 + c0 * 16, Abase, K, r0, c0, ko, ok0, b0, h0, w0);
            stageA<CONV>(AsmU + off + r1 * 80 + c1 * 16, Abase, K, r1, c1, ko, ok1, b1, h1, w1);
            cp16(BsmU + off + r0 * 80 + c0 * 16, Bbase + (size_t)r0 * K + ko + c0 * 8);
            cp16(BsmU + off + r1 * 80 + c1 * 16, Bbase + (size_t)r1 * K + ko + c1 * 8);
            CP_COMMIT();
        }
        const uint32_t Abuf = AsmU + (uint32_t)buf * 10240;
        const uint32_t Bbuf = BsmU + (uint32_t)buf * 10240;
        #pragma unroll
        for (int ks = 0; ks < 2; ks++) {
            unsigned af[4][4], bf[4][2];
            #pragma unroll
            for (int t = 0; t < 4; t++) {
                const uint32_t addr = Abuf + (uint32_t)(wm + t * 16 + a_row) * 80
                                    + (uint32_t)(ks * 16 + a_kc * 8) * 2;
                ldsm4(af[t][0], af[t][1], af[t][2], af[t][3], addr);
            }
            #pragma unroll
            for (int u2 = 0; u2 < 2; u2++) {
                const uint32_t addr = Bbuf + (uint32_t)(wn + u2 * 16 + b_row) * 80
                                    + (uint32_t)(ks * 16 + b_kc * 8) * 2;
                ldsm4(bf[2 * u2][0], bf[2 * u2][1], bf[2 * u2 + 1][0], bf[2 * u2 + 1][1], addr);
            }
            #pragma unroll
            for (int t = 0; t < 4; t++)
                #pragma unroll
                for (int u = 0; u < 4; u++)
                    mma16(acc[t][u], af[t], bf[u]);
        }
        buf = (buf == 2) ? 0 : buf + 1;
        nbuf = (nbuf == 2) ? 0 : nbuf + 1;
    }

    // ---- epilogue ----
    #pragma unroll
    for (int t = 0; t < 4; t++) {
        const int row0 = bm + wm + t * 16 + (lane >> 2);
        #pragma unroll
        for (int u = 0; u < 4; u++) {
            const int col = bn + wn + u * 8 + ((lane & 3) << 1);
            float b0f = 0.f, b1f = 0.f;
            if (MODE >= 1) { b0f = bias[col]; b1f = bias[col + 1]; }
            #pragma unroll
            for (int h = 0; h < 2; h++) {
                const int row = row0 + h * 8;
                if (row >= M) continue;
                float v0 = acc[t][u][h * 2 + 0] + b0f;
                float v1 = acc[t][u][h * 2 + 1] + b1f;
                if (MODE == 2) { v0 = gelu_exact(v0); v1 = gelu_exact(v1); }
                if (MODE == 3) {
                    const float* rr = res + (size_t)row * N + col;
                    v0 = v0 * gamma[col]     + rr[0];
                    v1 = v1 * gamma[col + 1] + rr[1];
                }
                if (Cf) *(float2*)&Cf[(size_t)row * N + col] = make_float2(v0, v1);
                if (Ch) *(__half2*)&Ch[(size_t)row * N + col] = __floats2half2_rn(v0, v1);
            }
        }
    }
}

// ---------------- fused weight prep: all transposes + f2h in ONE kernel ----------------
__global__ void prep_weights_kernel(
    const float* __restrict__ pw1, const float* __restrict__ pw2,
    const float* __restrict__ qkv, const float* __restrict__ ugkv,
    const float* __restrict__ ugq, const float* __restrict__ gbkv,
    const float* __restrict__ gbq, const float* __restrict__ proj,
    const float* __restrict__ convw, const float* __restrict__ gtok,
    __half* __restrict__ pw1T, __half* __restrict__ pw2T,
    __half* __restrict__ qkvT, __half* __restrict__ ugkvT,
    __half* __restrict__ ugqT, __half* __restrict__ gbkvT,
    __half* __restrict__ gbqT, __half* __restrict__ projT,
    __half* __restrict__ convT, __half* __restrict__ gtokh)
{
    int idx = blockIdx.x * blockDim.x + threadIdx.x;
    if (idx < 589824) {
        int n = idx / 384, k = idx % 384;
        pw1T[idx] = __float2half(pw1[(size_t)k * 1536 + n]); return;
    }
    idx -= 589824;
    if (idx < 589824) {
        int n = idx / 1536, k = idx % 1536;
        pw2T[idx] = __float2half(pw2[(size_t)k * 384 + n]); return;
    }
    idx -= 589824;
    if (idx < 442368) {
        int n = idx / 384, k = idx % 384;
        qkvT[idx] = __float2half(qkv[(size_t)k * 1152 + n]); return;
    }
    idx -= 442368;
    if (idx < 294912) {
        int n = idx / 384, k = idx % 384;
        ugkvT[idx] = __float2half(ugkv[(size_t)k * 768 + n]); return;
    }
    idx -= 294912;
    if (idx < 147456) {
        int n = idx / 384, k = idx % 384;
        ugqT[idx] = __float2half(ugq[(size_t)k * 384 + n]); return;
    }
    idx -= 147456;
    if (idx < 294912) {
        int n = idx / 384, k = idx % 384;
        gbkvT[idx] = __float2half(gbkv[(size_t)k * 768 + n]); return;
    }
    idx -= 294912;
    if (idx < 147456) {
        int n = idx / 384, k = idx % 384;
        gbqT[idx] = __float2half(gbq[(size_t)k * 384 + n]); return;
    }
    idx -= 147456;
    if (idx < 147456) {
        int n = idx / 384, k = idx % 384;
        projT[idx] = __float2half(proj[(size_t)k * 384 + n]); return;
    }
    idx -= 147456;
    if (idx < 1327104) {
        int o = idx / 3456, j = idx % 3456;
        int kk = j / 384, i = j % 384;
        convT[idx] = __float2half(convw[(size_t)o * 3456 + i * 9 + kk]); return;
    }
    idx -= 1327104;
    if (idx < 301056) {
        gtokh[idx] = __float2half(gtok[idx]);
    }
}
#define PREP_TOTAL 4282368

// ---------------- dwconv 3x3 depthwise + LN(1e-6) -> fp16; also emits x as fp16 ----------
__global__ void dwconv_ln_kernel(const float* __restrict__ x,
                                 const float* __restrict__ dw, const float* __restrict__ db,
                                 const float* __restrict__ gam, const float* __restrict__ bet,
                                 __half* __restrict__ out, __half* __restrict__ xh)
{
    __shared__ float sred[64];
    const int pix = blockIdx.x;
    const int b = pix / 3136, hw = pix % 3136;
    const int h = hw / 56, w = hw % 56;
    const int tid = threadIdx.x;
    float v[3];
    float s = 0.f, s2 = 0.f;
    #pragma unroll
    for (int r = 0; r < 3; r++) {
        int c = tid + r * 128;
        float acc = db[c];
        float ctr = 0.f;
        #pragma unroll
        for (int ky = 0; ky < 3; ky++) {
            int hh = h + ky - 1;
            if ((unsigned)hh >= 56u) continue;
            #pragma unroll
            for (int kx = 0; kx < 3; kx++) {
                int ww = w + kx - 1;
                if ((unsigned)ww >= 56u) continue;
                float xv = x[((size_t)b * 3136 + hh * 56 + ww) * 384 + c];
                if (ky == 1 && kx == 1) ctr = xv;
                acc = fmaf(xv, dw[c * 9 + ky * 3 + kx], acc);
            }
        }
        xh[(size_t)pix * 384 + c] = __float2half(ctr);
        v[r] = acc; s += acc; s2 = fmaf(acc, acc, s2);
    }
    int lane = tid & 31, warp = tid >> 5;
    #pragma unroll
    for (int off = 16; off; off >>= 1) {
        s  += __shfl_xor_sync(0xffffffffu, s, off);
        s2 += __shfl_xor_sync(0xffffffffu, s2, off);
    }
    if (lane == 0) { sred[warp] = s; sred[warp + 32] = s2; }
    __syncthreads();
    if (warp == 0) {
        float a  = (lane < 4) ? sred[lane] : 0.f;
        float b2 = (lane < 4) ? sred[lane + 32] : 0.f;
        #pragma unroll
        for (int off = 2; off; off >>= 1) {
            a  += __shfl_xor_sync(0xffffffffu, a, off);
            b2 += __shfl_xor_sync(0xffffffffu, b2, off);
        }
        if (lane == 0) { sred[0] = a; sred[1] = b2; }
    }
    __syncthreads();
    float mean = sred[0] * (1.f / 384.f);
    float var  = sred[1] * (1.f / 384.f) - mean * mean;
    float rstd = rsqrtf(var + 1e-6f);
    #pragma unroll
    for (int r = 0; r < 3; r++) {
        int c = tid + r * 128;
        out[(size_t)pix * 384 + c] = __float2half((v[r] - mean) * rstd * gam[c] + bet[c]);
    }
}

// ---------------- fused LN(1e-5)+ReLU+AvgPool2(2,2): [16,28,28,384]f32 -> [16,14,14,384]f16
__global__ void ln_relu_pool_kernel(const float* __restrict__ in,
                                    const float* __restrict__ gam, const float* __restrict__ bet,
                                    __half* __restrict__ out)
{
    __shared__ float sred[4][4][2];
    const int opix = blockIdx.x;
    const int b = opix / 196, q = opix % 196;
    const int ho = q / 14, wo = q % 14;
    const int tid = threadIdx.x;
    const int lane = tid & 31, warp = tid >> 5;

    size_t ibase[4];
    #pragma unroll
    for (int pp = 0; pp < 4; pp++) {
        int hi = 2 * ho + (pp >> 1), wi = 2 * wo + (pp & 1);
        ibase[pp] = (((size_t)b * 28 + hi) * 28 + wi) * 384;
    }
    float v[4][3];
    float s[4] = {0.f, 0.f, 0.f, 0.f}, s2[4] = {0.f, 0.f, 0.f, 0.f};
    #pragma unroll
    for (int pp = 0; pp < 4; pp++) {
        #pragma unroll
        for (int r = 0; r < 3; r++) {
            float a = in[ibase[pp] + tid + r * 128];
            v[pp][r] = a; s[pp] += a; s2[pp] = fmaf(a, a, s2[pp]);
        }
    }
    #pragma unroll
    for (int pp = 0; pp < 4; pp++) {
        float a = s[pp], c = s2[pp];
        #pragma unroll
        for (int off = 16; off; off >>= 1) {
            a += __shfl_xor_sync(0xffffffffu, a, off);
            c += __shfl_xor_sync(0xffffffffu, c, off);
        }
        if (lane == 0) { sred[warp][pp][0] = a; sred[warp][pp][1] = c; }
    }
    __syncthreads();
    float mean[4], rstd[4];
    #pragma unroll
    for (int pp = 0; pp < 4; pp++) {
        float a = sred[0][pp][0] + sred[1][pp][0] + sred[2][pp][0] + sred[3][pp][0];
        float c = sred[0][pp][1] + sred[1][pp][1] + sred[2][pp][1] + sred[3][pp][1];
        float m = a * (1.f / 384.f);
        mean[pp] = m;
        rstd[pp] = rsqrtf(c * (1.f / 384.f) - m * m + 1e-5f);
    }
    #pragma unroll
    for (int r = 0; r < 3; r++) {
        int c = tid + r * 128;
        float g = gam[c], be = bet[c];
        float acc = 0.f;
        #pragma unroll
        for (int pp = 0; pp < 4; pp++) {
            float val = (v[pp][r] - mean[pp]) * rstd[pp] * g + be;
            acc += fmaxf(val, 0.f);
        }
        out[(size_t)opix * 384 + c] = __float2half(0.25f * acc);
    }
}

// ---------------- AvgPool2d(2,2) NHWC fp16 -> fp16 (half2-vectorized) ----------------
__global__ void avgpool2h_kernel(const __half* __restrict__ in, __half* __restrict__ out,
                                 int B_, int Ho, int Wo)
{
    int idx = blockIdx.x * blockDim.x + threadIdx.x;
    int total = B_ * Ho * Wo * 192;
    if (idx >= total) return;
    int c2 = idx % 192; int t = idx / 192;
    int wo = t % Wo; t /= Wo;
    int ho = t % Ho; int b = t / Ho;
    int Hi = Ho * 2, Wi = Wo * 2;
    const __half2* p = (const __half2*)(in + (((size_t)b * Hi + 2 * ho) * Wi + 2 * wo) * 384) + c2;
    const size_t rs = (size_t)Wi * 192;
    float2 a0 = __half22float2(p[0]);
    float2 a1 = __half22float2(p[192]);
    float2 a2 = __half22float2(p[rs]);
    float2 a3 = __half22float2(p[rs + 192]);
    ((__half2*)out)[idx] = __floats2half2_rn(0.25f * (a0.x + a1.x + a2.x + a3.x),
                                             0.25f * (a0.y + a1.y + a2.y + a3.y));
}

// ---------------- MHA v2: warp per query-PAIR; lane-per-key scores; fp16 K/V ----------
__global__ void mha_kernel(const float* __restrict__ q, const __half* __restrict__ qh, int qs,
                           const __half* __restrict__ kh, int ks,
                           const __half* __restrict__ vh, int vs,
                           float* __restrict__ of, __half* __restrict__ oh, int os,
                           int Nq, int Nk, const __half* __restrict__ addsrc)
{
    extern __shared__ float sm[];
    float2* ksh2 = (float2*)sm;
    float2* vsh2 = ksh2 + (size_t)Nk * 32;
    const int nw = blockDim.x >> 5;
    float2* qbase = vsh2 + (size_t)Nk * 32;
    float*  scbase = (float*)(qbase + nw * 64);

    const int bh = blockIdx.x;
    const int b = bh / 6, h = bh % 6;
    const int tid = threadIdx.x;
    const int warp = tid >> 5, lane = tid & 31;

    const __half* kb = kh + (size_t)b * Nk * ks + h * 64;
    const __half* vb = vh + (size_t)b * Nk * vs + h * 64;
    for (int idx = tid; idx < Nk * 32; idx += blockDim.x) {
        int j = idx >> 5, d2 = idx & 31;
        ksh2[idx] = __half22float2(*(const __half2*)(kb + (size_t)j * ks + 2 * d2));
        vsh2[idx] = __half22float2(*(const __half2*)(vb + (size_t)j * vs + 2 * d2));
    }
    __syncthreads();

    float2* qa2 = qbase + warp * 64;
    float2* qb2 = qa2 + 32;
    float* sca = scbase + warp * 2 * Nk;
    float* scb = sca + Nk;

    const int npairs = (Nq + 1) >> 1;
    for (int qp = blockIdx.y * nw + warp; qp < npairs; qp += gridDim.y * nw) {
        const int qia = 2 * qp;
        const int qib = qia + 1;
        const bool hasb = qib < Nq;
        const int qibc = hasb ? qib : qia;
        {
            float a0, a1, b0, b1;
            if (qh) {
                __half2 ha = *(const __half2*)(qh + ((size_t)b * Nq + qia) * qs + h * 64 + 2 * lane);
                __half2 hb = *(const __half2*)(qh + ((size_t)b * Nq + qibc) * qs + h * 64 + 2 * lane);
                float2 fa = __half22float2(ha), fb = __half22float2(hb);
                a0 = fa.x; a1 = fa.y; b0 = fb.x; b1 = fb.y;
            } else {
                float2 fa = *(const float2*)(q + ((size_t)b * Nq + qia) * qs + h * 64 + 2 * lane);
                float2 fb = *(const float2*)(q + ((size_t)b * Nq + qibc) * qs + h * 64 + 2 * lane);
                a0 = fa.x; a1 = fa.y; b0 = fb.x; b1 = fb.y;
            }
            qa2[lane] = make_float2(a0 * 0.125f, a1 * 0.125f);
            qb2[lane] = make_float2(b0 * 0.125f, b1 * 0.125f);
        }
        __syncwarp();

        float ma = -1e30f, mb = -1e30f;
        for (int j0 = 0; j0 < Nk; j0 += 32) {
            const int j = j0 + lane;
            const float2* kj = ksh2 + (size_t)j * 32;
            float sa0 = 0.f, sa1 = 0.f, sb0 = 0.f, sb1 = 0.f;
            int d2 = lane;
            #pragma unroll 8
            for (int dd = 0; dd < 32; dd += 2) {
                float2 k2 = kj[d2];
                float2 qa = qa2[d2];
                float2 qb = qb2[d2];
                sa0 = fmaf(k2.x, qa.x, fmaf(k2.y, qa.y, sa0));
                sb0 = fmaf(k2.x, qb.x, fmaf(k2.y, qb.y, sb0));
                int d2b = (d2 + 1) & 31;
                float2 k3 = kj[d2b];
                float2 qa3 = qa2[d2b];
                float2 qb3 = qb2[d2b];
                sa1 = fmaf(k3.x, qa3.x, fmaf(k3.y, qa3.y, sa1));
                sb1 = fmaf(k3.x, qb3.x, fmaf(k3.y, qb3.y, sb1));
                d2 = (d2 + 2) & 31;
            }
            float sa = sa0 + sa1, sb = sb0 + sb1;
            if (j < Nk) {
                sca[j] = sa; scb[j] = sb;
                ma = fmaxf(ma, sa); mb = fmaxf(mb, sb);
            }
        }
        #pragma unroll
        for (int off = 16; off; off >>= 1) {
            ma = fmaxf(ma, __shfl_xor_sync(0xffffffffu, ma, off));
            mb = fmaxf(mb, __shfl_xor_sync(0xffffffffu, mb, off));
        }
        float suma = 0.f, sumb = 0.f;
        for (int j = lane; j < Nk; j += 32) {
            float ea = expf(sca[j] - ma); sca[j] = ea; suma += ea;
            float eb = expf(scb[j] - mb); scb[j] = eb; sumb += eb;
        }
        #pragma unroll
        for (int off = 16; off; off >>= 1) {
            suma += __shfl_xor_sync(0xffffffffu, suma, off);
            sumb += __shfl_xor_sync(0xffffffffu, sumb, off);
        }
        const float inva = 1.f / suma, invb = 1.f / sumb;
        __syncwarp();

        float2 oa = make_float2(0.f, 0.f), ob = make_float2(0.f, 0.f);
        const float2* vrow = vsh2 + lane;
        for (int j = 0; j < Nk; j++) {
            float pa = sca[j], pb = scb[j];
            float2 v2 = vrow[(size_t)j * 32];
            oa.x = fmaf(pa, v2.x, oa.x); oa.y = fmaf(pa, v2.y, oa.y);
            ob.x = fmaf(pb, v2.x, ob.x); ob.y = fmaf(pb, v2.y, ob.y);
        }
        oa.x *= inva; oa.y *= inva; ob.x *= invb; ob.y *= invb;
        if (addsrc) {
            float2 ra = __half22float2(*(const __half2*)(addsrc + ((size_t)b * Nq + qia) * 384 + h * 64 + 2 * lane));
            oa.x += ra.x; oa.y += ra.y;
            if (hasb) {
                float2 rb = __half22float2(*(const __half2*)(addsrc + ((size_t)b * Nq + qib) * 384 + h * 64 + 2 * lane));
                ob.x += rb.x; ob.y += rb.y;
            }
        }
        const size_t oba = ((size_t)b * Nq + qia) * os + h * 64 + 2 * lane;
        if (of) {
            *(float2*)&of[oba] = oa;
            if (hasb) *(float2*)&of[oba + os] = ob;
        }
        if (oh) {
            *(__half2*)&oh[oba] = __floats2half2_rn(oa.x, oa.y);
            if (hasb) *(__half2*)&oh[oba + os] = __floats2half2_rn(ob.x, ob.y);
        }
        __syncwarp();
    }
}

// ---------------- launch ----------------
extern "C" void kernel_launch(void* const* d_in, const int* in_sizes, int n_in,
                              void* d_out, int out_size)
{
    const float* x        = (const float*)d_in[0];
    const float* gtok     = (const float*)d_in[1];
    const float* we_dw_w  = (const float*)d_in[2];
    const float* we_dw_b  = (const float*)d_in[3];
    const float* we_ln_g  = (const float*)d_in[4];
    const float* we_ln_b  = (const float*)d_in[5];
    const float* we_pw1_w = (const float*)d_in[6];
    const float* we_pw1_b = (const float*)d_in[7];
    const float* we_pw2_w = (const float*)d_in[8];
    const float* we_pw2_b = (const float*)d_in[9];
    const float* we_gamma = (const float*)d_in[10];
    const float* cb_conv_w= (const float*)d_in[11];
    const float* cb_ln_g  = (const float*)d_in[12];
    const float* cb_ln_b  = (const float*)d_in[13];
    const float* ga_qkv_w = (const float*)d_in[14];
    const float* ug_kv_w  = (const float*)d_in[15];
    const float* ug_q_w   = (const float*)d_in[16];
    const float* gb_kv_w  = (const float*)d_in[17];
    const float* gb_q_w   = (const float*)d_in[18];
    const float* proj_w   = (const float*)d_in[19];
    const float* proj_b   = (const float*)d_in[20];

    float* out = (float*)d_out;
    float* gt_out = out + GT_OFF;

    __half *ln1h, *h1h, *pool1h, *xdh, *xdsh, *gtokh, *gth, *xh, *qxh, *xsumh;
    __half *qkvh, *kv2h, *kv3h;
    __half *pw1T, *pw2T, *qkvT, *ugkvT, *ugqT, *gbkvT, *gbqT, *projT, *convT;
    float *c2pre, *qg;
    cudaGetSymbolAddress((void**)&ln1h,   h_ln1);
    cudaGetSymbolAddress((void**)&h1h,    h_h1);
    cudaGetSymbolAddress((void**)&pool1h, h_pool1);
    cudaGetSymbolAddress((void**)&xdh,    h_xd);
    cudaGetSymbolAddress((void**)&xdsh,   h_xds);
    cudaGetSymbolAddress((void**)&gtokh,  h_gtok);
    cudaGetSymbolAddress((void**)&gth,    h_gt);
    cudaGetSymbolAddress((void**)&xh,     h_x);
    cudaGetSymbolAddress((void**)&qxh,    h_qx);
    cudaGetSymbolAddress((void**)&xsumh,  h_xsum);
    cudaGetSymbolAddress((void**)&qkvh,   h_qkv);
    cudaGetSymbolAddress((void**)&kv2h,   h_kv2);
    cudaGetSymbolAddress((void**)&kv3h,   h_kv3);
    cudaGetSymbolAddress((void**)&c2pre,  g_c2pre);
    cudaGetSymbolAddress((void**)&qg,     g_qg);
    cudaGetSymbolAddress((void**)&pw1T,   w_pw1T);
    cudaGetSymbolAddress((void**)&pw2T,   w_pw2T);
    cudaGetSymbolAddress((void**)&qkvT,   w_qkvT);
    cudaGetSymbolAddress((void**)&ugkvT,  w_ugkvT);
    cudaGetSymbolAddress((void**)&ugqT,   w_ugqT);
    cudaGetSymbolAddress((void**)&gbkvT,  w_gbkvT);
    cudaGetSymbolAddress((void**)&gbqT,   w_gbqT);
    cudaGetSymbolAddress((void**)&projT,  w_projT);
    cudaGetSymbolAddress((void**)&convT,  w_convT);
    __half* xlocalh = ln1h;   // reuse: ln1h is dead after MLP1

    const int SMEM_TG  = 61440;
    const int SMEM196 = 2 * 196 * 256 + 4 * (512 + 8 * 196);   // 108672
    const int SMEM49  = 2 * 49  * 256 + 4 * (512 + 8 * 49);    // 28704
    cudaFuncSetAttribute(mha_kernel, cudaFuncAttributeMaxDynamicSharedMemorySize, SMEM196);
    cudaFuncSetAttribute((hgemm<0,0>), cudaFuncAttributeMaxDynamicSharedMemorySize, SMEM_TG);
    cudaFuncSetAttribute((hgemm<1,0>), cudaFuncAttributeMaxDynamicSharedMemorySize, SMEM_TG);
    cudaFuncSetAttribute((hgemm<2,0>), cudaFuncAttributeMaxDynamicSharedMemorySize, SMEM_TG);
    cudaFuncSetAttribute((hgemm<3,0>), cudaFuncAttributeMaxDynamicSharedMemorySize, SMEM_TG);
    cudaFuncSetAttribute((hgemm<0,1>), cudaFuncAttributeMaxDynamicSharedMemorySize, SMEM_TG);

    // ---- fused weight prep (one launch) ----
    prep_weights_kernel<<<(PREP_TOTAL + 255) / 256, 256>>>(
        we_pw1_w, we_pw2_w, ga_qkv_w, ug_kv_w, ug_q_w, gb_kv_w, gb_q_w, proj_w,
        cb_conv_w, gtok,
        pw1T, pw2T, qkvT, ugkvT, ugqT, gbkvT, gbqT, projT, convT, gtokh);

    // ConvEncoder: dwconv + LN -> fp16 (also emits x fp16)
    dwconv_ln_kernel<<<50176, 128>>>(x, we_dw_w, we_dw_b, we_ln_g, we_ln_b, ln1h, xh);

    // MLP1: gelu(ln1 @ pw1 + b1) -> fp16 hidden
    hgemm<2,0><<<dim3(12, 392), 256, SMEM_TG>>>(ln1h, pw1T, we_pw1_b, nullptr, nullptr,
                                                nullptr, h1h, 50176, 1536, 384);
    // MLP2 + layer-scale + residual -> fp16 xlocal (reuses ln1h)
    hgemm<3,0><<<dim3(3, 392), 256, SMEM_TG>>>(h1h, pw2T, we_pw2_b, we_gamma, x,
                                               nullptr, xlocalh, 50176, 384, 1536);
    // down_1: 56->28 fp16->fp16
    avgpool2h_kernel<<<(2408448 + 255) / 256, 256>>>(xlocalh, pool1h, 16, 28, 28);

    // ConvBNReLU: implicit-GEMM conv (no im2col), then fused LN+ReLU+pool -> fp16 tokens
    hgemm<0,1><<<dim3(3, 98), 256, SMEM_TG>>>(pool1h, convT, nullptr, nullptr, nullptr,
                                              c2pre, nullptr, 12544, 384, 3456);
    ln_relu_pool_kernel<<<3136, 128>>>(c2pre, cb_ln_g, cb_ln_b, xdh);

    // global aggregation MHSA (qkv fp16)
    hgemm<0,0><<<dim3(9, 25), 256, SMEM_TG>>>(xdh, qkvT, nullptr, nullptr, nullptr,
                                              nullptr, qkvh, 3136, 1152, 384);
    mha_kernel<<<dim3(96, 8), 128, SMEM196>>>(nullptr, qkvh, 1152, qkvh + 384, 1152,
                                              qkvh + 768, 1152,
                                              nullptr, xdsh, 384, 196, 196, nullptr);

    // global token update (kv2 fp16; qg fp32)
    hgemm<0,0><<<dim3(6, 25), 256, SMEM_TG>>>(xdsh, ugkvT, nullptr, nullptr, nullptr,
                                              nullptr, kv2h, 3136, 768, 384);
    hgemm<0,0><<<dim3(3, 7), 256, SMEM_TG>>>(gtokh, ugqT, nullptr, nullptr, nullptr,
                                             qg, nullptr, 784, 384, 384);
    mha_kernel<<<dim3(96, 2), 128, SMEM196>>>(qg, nullptr, 384, kv2h, 768, kv2h + 384, 768,
                                              gt_out, gth, 384, 49, 196, nullptr);

    // global broadcast (kv3 fp16)
    hgemm<0,0><<<dim3(6, 7), 256, SMEM_TG>>>(gth, gbkvT, nullptr, nullptr, nullptr,
                                             nullptr, kv3h, 784, 768, 384);
    hgemm<0,0><<<dim3(3, 392), 256, SMEM_TG>>>(xh, gbqT, nullptr, nullptr, nullptr,
                                               nullptr, qxh, 50176, 384, 384);
    // x_global + x_local(fp16) fused into MHA output -> fp16 xsum
    mha_kernel<<<dim3(96, 64), 128, SMEM49>>>(nullptr, qxh, 384, kv3h, 768, kv3h + 384, 768,
                                              nullptr, xsumh, 384, 3136, 49, xlocalh);

    // final projection: xsum @ proj_w + proj_b -> out
    hgemm<1,0><<<dim3(3, 392), 256, SMEM_TG>>>(xsumh, projT, proj_b, nullptr, nullptr,
                                               out, nullptr, 50176, 384, 384);
}

// round 16
// speedup vs baseline: 1.2093x; 1.0101x over previous
#include <cuda_runtime.h>
#include <cuda_fp16.h>
#include <math.h>
#include <stdint.h>

// ---------------- constants ----------------
#define GT_OFF 19267584      // 16*3136*384

// ---------------- scratch (device globals; allocation-free) ----------------
__device__ __half h_ln1[19267584];     // dwconv+LN out; later reused as xlocal fp16
__device__ __half h_h1[77070336];      // MLP hidden
__device__ __half h_pool1[4816896];    // down_1 fp16 (implicit-conv A operand)
__device__ __half h_xd[1204224];       // downsampled tokens
__device__ __half h_xds[1204224];      // global-agg MHA out
__device__ __half h_gtok[301056];      // global_token fp16
__device__ __half h_gt[301056];        // updated global token fp16
__device__ __half h_x[19267584];       // x fp16
__device__ __half h_qx[19267584];      // q for global broadcast (fp16)
__device__ __half h_xsum[19267584];    // xlocal + xglobal
__device__ __half h_qkv[3612672];      // [B,196,1152] fp16
__device__ __half h_kv2[2408448];      // [B,196,768] fp16
__device__ __half h_kv3[602112];       // [B,49,768] fp16
__device__ float g_c2pre[4816896];     // conv2 pre-LN
__device__ float g_qg[301056];         // [B,49,384]
__device__ __half w_pw1T[589824];
__device__ __half w_pw2T[589824];
__device__ __half w_qkvT[442368];
__device__ __half w_ugkvT[294912];
__device__ __half w_ugqT[147456];
__device__ __half w_gbkvT[294912];
__device__ __half w_gbqT[147456];
__device__ __half w_projT[147456];
__device__ __half w_convT[1327104];

// ---------------- helpers ----------------
__device__ __forceinline__ float gelu_exact(float x){
    return 0.5f * x * (1.0f + erff(x * 0.70710678118654752f));
}
__device__ __forceinline__ uint32_t smem_u32(const void* p) {
    uint32_t a;
    asm("{ .reg .u64 t; cvta.to.shared.u64 t, %1; cvt.u32.u64 %0, t; }" : "=r"(a) : "l"(p));
    return a;
}
__device__ __forceinline__ void mma16(float* d, const unsigned* a, const unsigned* b){
    asm volatile("mma.sync.aligned.m16n8k16.row.col.f32.f16.f16.f32 "
        "{%0,%1,%2,%3},{%4,%5,%6,%7},{%8,%9},{%0,%1,%2,%3};"
        : "+f"(d[0]), "+f"(d[1]), "+f"(d[2]), "+f"(d[3])
        : "r"(a[0]), "r"(a[1]), "r"(a[2]), "r"(a[3]), "r"(b[0]), "r"(b[1]));
}
__device__ __forceinline__ void ldsm4(unsigned& r0, unsigned& r1, unsigned& r2, unsigned& r3,
                                      uint32_t addr){
    asm volatile("ldmatrix.sync.aligned.m8n8.x4.shared.b16 {%0,%1,%2,%3}, [%4];"
        : "=r"(r0), "=r"(r1), "=r"(r2), "=r"(r3) : "r"(addr));
}
__device__ __forceinline__ void cp16(uint32_t s, const void* g) {
    asm volatile("cp.async.cg.shared.global [%0], [%1], 16;" :: "r"(s), "l"(g));
}
__device__ __forceinline__ void cp16z(uint32_t s, const void* g, int sz) {
    asm volatile("cp.async.cg.shared.global [%0], [%1], 16, %2;" :: "r"(s), "l"(g), "r"(sz));
}
#define CP_COMMIT() asm volatile("cp.async.commit_group;" ::: "memory")
#define CP_WAIT(n)  asm volatile("cp.async.wait_group %0;" :: "n"(n) : "memory")

// A-operand staging: dense (CONV=0) or implicit 3x3 SAME conv over [16,28,28,384] (CONV=1)
template<int CONV>
__device__ __forceinline__ void stageA(uint32_t dst, const __half* __restrict__ Abase,
                                       int K, int r, int c, int ko, bool rowok,
                                       int b, int h, int w)
{
    if (!CONV) {
        if (rowok) cp16(dst, Abase + (size_t)r * K + ko + c * 8);
    } else {
        int k = ko + c * 8;
        int kk = k / 384;            // tap index 0..8
        int cin = k - kk * 384;      // channel (8-aligned)
        int ky = kk / 3, kx = kk - 3 * ky;
        int hh = h + ky - 1, ww = w + kx - 1;
        bool inb = ((unsigned)hh < 28u) && ((unsigned)ww < 28u);
        const __half* src = inb
            ? Abase + (((size_t)(b * 28 + hh) * 28 + ww) * 384 + cin)
            : Abase;
        cp16z(dst, src, inb ? 16 : 0);
    }
}

// ---------------- FP16 GEMM: mma.m16n8k16 + ldmatrix + cp.async 3-stage ring (K32) -------
// CTA tile 128x128, 256 threads (8 warps x 64x32). smem 3 x (A 128x40h + B 128x40h) = 61440 B.
// MODE 0: C = A@B ; 1: +bias ; 2: gelu(+bias) ; 3: (+bias)*gamma + res
template<int MODE, int CONV>
__global__ void __launch_bounds__(256, 2) hgemm(
    const __half* __restrict__ A, const __half* __restrict__ BT,
    const float* __restrict__ bias, const float* __restrict__ gamma,
    const float* __restrict__ res,
    float* __restrict__ Cf, __half* __restrict__ Ch,
    int M, int N, int K)
{
    extern __shared__ __half smh[];
    __half* Asm = smh;              // [3][128][40]
    __half* Bsm = smh + 3 * 5120;   // [3][128][40]
    const uint32_t AsmU = smem_u32(Asm);
    const uint32_t BsmU = smem_u32(Bsm);

    const int tid  = threadIdx.x;
    const int warp = tid >> 5, lane = tid & 31;
    const int wm = (warp >> 2) * 64;
    const int wn = (warp & 3) * 32;
    const int bm = blockIdx.y * 128;
    const int bn = blockIdx.x * 128;

    float acc[4][4][4];
    #pragma unroll
    for (int t = 0; t < 4; t++)
        #pragma unroll
        for (int u = 0; u < 4; u++)
            #pragma unroll
            for (int e = 0; e < 4; e++) acc[t][u][e] = 0.f;

    const int maxrowA = M - bm;
    const __half* Abase = CONV ? A : (A + (size_t)bm * K);
    const __half* Bbase = BT + (size_t)bn * K;

    const int cid0 = tid * 2;
    const int r0 = cid0 >> 2,       c0 = (cid0 & 3);
    const int r1 = (cid0 + 1) >> 2, c1 = ((cid0 + 1) & 3);
    const bool ok0 = r0 < maxrowA, ok1 = r1 < maxrowA;
    int b0 = 0, h0 = 0, w0 = 0, b1 = 0, h1 = 0, w1 = 0;
    if (CONV) {
        int p0 = bm + r0; b0 = p0 / 784; int q0 = p0 - b0 * 784; h0 = q0 / 28; w0 = q0 - h0 * 28;
        int p1 = bm + r1; b1 = p1 / 784; int q1 = p1 - b1 * 784; h1 = q1 / 28; w1 = q1 - h1 * 28;
    }

    const int a_row = lane & 15;
    const int a_kc  = (lane >> 4) & 1;
    const int b_row = (lane & 7) | ((lane >> 1) & 8);
    const int b_kc  = (lane >> 3) & 1;

    const int T = K >> 5;

    // prologue
    {
        stageA<CONV>(AsmU + r0 * 80 + c0 * 16, Abase, K, r0, c0, 0, ok0, b0, h0, w0);
        stageA<CONV>(AsmU + r1 * 80 + c1 * 16, Abase, K, r1, c1, 0, ok1, b1, h1, w1);
        cp16(BsmU + r0 * 80 + c0 * 16, Bbase + (size_t)r0 * K + c0 * 8);
        cp16(BsmU + r1 * 80 + c1 * 16, Bbase + (size_t)r1 * K + c1 * 8);
        CP_COMMIT();
        if (T > 1) {
            stageA<CONV>(AsmU + 10240 + r0 * 80 + c0 * 16, Abase, K, r0, c0, 32, ok0, b0, h0, w0);
            stageA<CONV>(AsmU + 10240 + r1 * 80 + c1 * 16, Abase, K, r1, c1, 32, ok1, b1, h1, w1);
            cp16(BsmU + 10240 + r0 * 80 + c0 * 16, Bbase + (size_t)r0 * K + 32 + c0 * 8);
            cp16(BsmU + 10240 + r1 * 80 + c1 * 16, Bbase + (size_t)r1 * K + 32 + c1 * 8);
            CP_COMMIT();
        }
    }

    int buf = 0, nbuf = (T > 2) ? 2 : (T == 2 ? 0 : 1);
    for (int it = 0; it < T; ++it) {
        if (it + 1 < T) CP_WAIT(1); else CP_WAIT(0);
        __syncthreads();
        if (it + 2 < T) {
            const int ko = (it + 2) << 5;
            const uint32_t off = (uint32_t)nbuf * 10240;
            stageA<CONV>(AsmU + off + r0 * 80 + c0 * 16, Abase, K, r0, c0, ko, ok0, b0, h0, w0);
            stageA<CONV>(AsmU + off + r1 * 80 + c1 * 16, Abase, K, r1, c1, ko, ok1, b1, h1, w1);
            cp16(BsmU + off + r0 * 80 + c0 * 16, Bbase + (size_t)r0 * K + ko + c0 * 8);
            cp16(BsmU + off + r1 * 80 + c1 * 16, Bbase + (size_t)r1 * K + ko + c1 * 8);
            CP_COMMIT();
        }
        const uint32_t Abuf = AsmU + (uint32_t)buf * 10240;
        const uint32_t Bbuf = BsmU + (uint32_t)buf * 10240;
        #pragma unroll
        for (int ks = 0; ks < 2; ks++) {
            unsigned af[4][4], bf[4][2];
            #pragma unroll
            for (int t = 0; t < 4; t++) {
                const uint32_t addr = Abuf + (uint32_t)(wm + t * 16 + a_row) * 80
                                    + (uint32_t)(ks * 16 + a_kc * 8) * 2;
                ldsm4(af[t][0], af[t][1], af[t][2], af[t][3], addr);
            }
            #pragma unroll
            for (int u2 = 0; u2 < 2; u2++) {
                const uint32_t addr = Bbuf + (uint32_t)(wn + u2 * 16 + b_row) * 80
                                    + (uint32_t)(ks * 16 + b_kc * 8) * 2;
                ldsm4(bf[2 * u2][0], bf[2 * u2][1], bf[2 * u2 + 1][0], bf[2 * u2 + 1][1], addr);
            }
            #pragma unroll
            for (int t = 0; t < 4; t++)
                #pragma unroll
                for (int u = 0; u < 4; u++)
                    mma16(acc[t][u], af[t], bf[u]);
        }
        buf = (buf == 2) ? 0 : buf + 1;
        nbuf = (nbuf == 2) ? 0 : nbuf + 1;
    }

    // ---- epilogue ----
    #pragma unroll
    for (int t = 0; t < 4; t++) {
        const int row0 = bm + wm + t * 16 + (lane >> 2);
        #pragma unroll
        for (int u = 0; u < 4; u++) {
            const int col = bn + wn + u * 8 + ((lane & 3) << 1);
            float b0f = 0.f, b1f = 0.f;
            if (MODE >= 1) { b0f = bias[col]; b1f = bias[col + 1]; }
            #pragma unroll
            for (int h = 0; h < 2; h++) {
                const int row = row0 + h * 8;
                if (row >= M) continue;
                float v0 = acc[t][u][h * 2 + 0] + b0f;
                float v1 = acc[t][u][h * 2 + 1] + b1f;
                if (MODE == 2) { v0 = gelu_exact(v0); v1 = gelu_exact(v1); }
                if (MODE == 3) {
                    const float* rr = res + (size_t)row * N + col;
                    v0 = v0 * gamma[col]     + rr[0];
                    v1 = v1 * gamma[col + 1] + rr[1];
                }
                if (Cf) *(float2*)&Cf[(size_t)row * N + col] = make_float2(v0, v1);
                if (Ch) *(__half2*)&Ch[(size_t)row * N + col] = __floats2half2_rn(v0, v1);
            }
        }
    }
}

// ---------------- fused weight prep: all transposes + f2h in ONE kernel ----------------
__global__ void prep_weights_kernel(
    const float* __restrict__ pw1, const float* __restrict__ pw2,
    const float* __restrict__ qkv, const float* __restrict__ ugkv,
    const float* __restrict__ ugq, const float* __restrict__ gbkv,
    const float* __restrict__ gbq, const float* __restrict__ proj,
    const float* __restrict__ convw, const float* __restrict__ gtok,
    __half* __restrict__ pw1T, __half* __restrict__ pw2T,
    __half* __restrict__ qkvT, __half* __restrict__ ugkvT,
    __half* __restrict__ ugqT, __half* __restrict__ gbkvT,
    __half* __restrict__ gbqT, __half* __restrict__ projT,
    __half* __restrict__ convT, __half* __restrict__ gtokh)
{
    int idx = blockIdx.x * blockDim.x + threadIdx.x;
    if (idx < 589824) {
        int n = idx / 384, k = idx % 384;
        pw1T[idx] = __float2half(pw1[(size_t)k * 1536 + n]); return;
    }
    idx -= 589824;
    if (idx < 589824) {
        int n = idx / 1536, k = idx % 1536;
        pw2T[idx] = __float2half(pw2[(size_t)k * 384 + n]); return;
    }
    idx -= 589824;
    if (idx < 442368) {
        int n = idx / 384, k = idx % 384;
        qkvT[idx] = __float2half(qkv[(size_t)k * 1152 + n]); return;
    }
    idx -= 442368;
    if (idx < 294912) {
        int n = idx / 384, k = idx % 384;
        ugkvT[idx] = __float2half(ugkv[(size_t)k * 768 + n]); return;
    }
    idx -= 294912;
    if (idx < 147456) {
        int n = idx / 384, k = idx % 384;
        ugqT[idx] = __float2half(ugq[(size_t)k * 384 + n]); return;
    }
    idx -= 147456;
    if (idx < 294912) {
        int n = idx / 384, k = idx % 384;
        gbkvT[idx] = __float2half(gbkv[(size_t)k * 768 + n]); return;
    }
    idx -= 294912;
    if (idx < 147456) {
        int n = idx / 384, k = idx % 384;
        gbqT[idx] = __float2half(gbq[(size_t)k * 384 + n]); return;
    }
    idx -= 147456;
    if (idx < 147456) {
        int n = idx / 384, k = idx % 384;
        projT[idx] = __float2half(proj[(size_t)k * 384 + n]); return;
    }
    idx -= 147456;
    if (idx < 1327104) {
        int o = idx / 3456, j = idx % 3456;
        int kk = j / 384, i = j % 384;
        convT[idx] = __float2half(convw[(size_t)o * 3456 + i * 9 + kk]); return;
    }
    idx -= 1327104;
    if (idx < 301056) {
        gtokh[idx] = __float2half(gtok[idx]);
    }
}
#define PREP_TOTAL 4282368

// ---------------- dwconv 3x3 depthwise + LN(1e-6) -> fp16; also emits x as fp16 ----------
__global__ void dwconv_ln_kernel(const float* __restrict__ x,
                                 const float* __restrict__ dw, const float* __restrict__ db,
                                 const float* __restrict__ gam, const float* __restrict__ bet,
                                 __half* __restrict__ out, __half* __restrict__ xh)
{
    __shared__ float sred[64];
    const int pix = blockIdx.x;
    const int b = pix / 3136, hw = pix % 3136;
    const int h = hw / 56, w = hw % 56;
    const int tid = threadIdx.x;
    float v[3];
    float s = 0.f, s2 = 0.f;
    #pragma unroll
    for (int r = 0; r < 3; r++) {
        int c = tid + r * 128;
        float acc = db[c];
        float ctr = 0.f;
        #pragma unroll
        for (int ky = 0; ky < 3; ky++) {
            int hh = h + ky - 1;
            if ((unsigned)hh >= 56u) continue;
            #pragma unroll
            for (int kx = 0; kx < 3; kx++) {
                int ww = w + kx - 1;
                if ((unsigned)ww >= 56u) continue;
                float xv = x[((size_t)b * 3136 + hh * 56 + ww) * 384 + c];
                if (ky == 1 && kx == 1) ctr = xv;
                acc = fmaf(xv, dw[c * 9 + ky * 3 + kx], acc);
            }
        }
        xh[(size_t)pix * 384 + c] = __float2half(ctr);
        v[r] = acc; s += acc; s2 = fmaf(acc, acc, s2);
    }
    int lane = tid & 31, warp = tid >> 5;
    #pragma unroll
    for (int off = 16; off; off >>= 1) {
        s  += __shfl_xor_sync(0xffffffffu, s, off);
        s2 += __shfl_xor_sync(0xffffffffu, s2, off);
    }
    if (lane == 0) { sred[warp] = s; sred[warp + 32] = s2; }
    __syncthreads();
    if (warp == 0) {
        float a  = (lane < 4) ? sred[lane] : 0.f;
        float b2 = (lane < 4) ? sred[lane + 32] : 0.f;
        #pragma unroll
        for (int off = 2; off; off >>= 1) {
            a  += __shfl_xor_sync(0xffffffffu, a, off);
            b2 += __shfl_xor_sync(0xffffffffu, b2, off);
        }
        if (lane == 0) { sred[0] = a; sred[1] = b2; }
    }
    __syncthreads();
    float mean = sred[0] * (1.f / 384.f);
    float var  = sred[1] * (1.f / 384.f) - mean * mean;
    float rstd = rsqrtf(var + 1e-6f);
    #pragma unroll
    for (int r = 0; r < 3; r++) {
        int c = tid + r * 128;
        out[(size_t)pix * 384 + c] = __float2half((v[r] - mean) * rstd * gam[c] + bet[c]);
    }
}

// ---------------- fused LN(1e-5)+ReLU+AvgPool2(2,2): [16,28,28,384]f32 -> [16,14,14,384]f16
__global__ void ln_relu_pool_kernel(const float* __restrict__ in,
                                    const float* __restrict__ gam, const float* __restrict__ bet,
                                    __half* __restrict__ out)
{
    __shared__ float sred[4][4][2];
    const int opix = blockIdx.x;
    const int b = opix / 196, q = opix % 196;
    const int ho = q / 14, wo = q % 14;
    const int tid = threadIdx.x;
    const int lane = tid & 31, warp = tid >> 5;

    size_t ibase[4];
    #pragma unroll
    for (int pp = 0; pp < 4; pp++) {
        int hi = 2 * ho + (pp >> 1), wi = 2 * wo + (pp & 1);
        ibase[pp] = (((size_t)b * 28 + hi) * 28 + wi) * 384;
    }
    float v[4][3];
    float s[4] = {0.f, 0.f, 0.f, 0.f}, s2[4] = {0.f, 0.f, 0.f, 0.f};
    #pragma unroll
    for (int pp = 0; pp < 4; pp++) {
        #pragma unroll
        for (int r = 0; r < 3; r++) {
            float a = in[ibase[pp] + tid + r * 128];
            v[pp][r] = a; s[pp] += a; s2[pp] = fmaf(a, a, s2[pp]);
        }
    }
    #pragma unroll
    for (int pp = 0; pp < 4; pp++) {
        float a = s[pp], c = s2[pp];
        #pragma unroll
        for (int off = 16; off; off >>= 1) {
            a += __shfl_xor_sync(0xffffffffu, a, off);
            c += __shfl_xor_sync(0xffffffffu, c, off);
        }
        if (lane == 0) { sred[warp][pp][0] = a; sred[warp][pp][1] = c; }
    }
    __syncthreads();
    float mean[4], rstd[4];
    #pragma unroll
    for (int pp = 0; pp < 4; pp++) {
        float a = sred[0][pp][0] + sred[1][pp][0] + sred[2][pp][0] + sred[3][pp][0];
        float c = sred[0][pp][1] + sred[1][pp][1] + sred[2][pp][1] + sred[3][pp][1];
        float m = a * (1.f / 384.f);
        mean[pp] = m;
        rstd[pp] = rsqrtf(c * (1.f / 384.f) - m * m + 1e-5f);
    }
    #pragma unroll
    for (int r = 0; r < 3; r++) {
        int c = tid + r * 128;
        float g = gam[c], be = bet[c];
        float acc = 0.f;
        #pragma unroll
        for (int pp = 0; pp < 4; pp++) {
            float val = (v[pp][r] - mean[pp]) * rstd[pp] * g + be;
            acc += fmaxf(val, 0.f);
        }
        out[(size_t)opix * 384 + c] = __float2half(0.25f * acc);
    }
}

// ---------------- AvgPool2d(2,2) NHWC fp16 -> fp16 (half2-vectorized) ----------------
__global__ void avgpool2h_kernel(const __half* __restrict__ in, __half* __restrict__ out,
                                 int B_, int Ho, int Wo)
{
    int idx = blockIdx.x * blockDim.x + threadIdx.x;
    int total = B_ * Ho * Wo * 192;
    if (idx >= total) return;
    int c2 = idx % 192; int t = idx / 192;
    int wo = t % Wo; t /= Wo;
    int ho = t % Ho; int b = t / Ho;
    int Hi = Ho * 2, Wi = Wo * 2;
    const __half2* p = (const __half2*)(in + (((size_t)b * Hi + 2 * ho) * Wi + 2 * wo) * 384) + c2;
    const size_t rs = (size_t)Wi * 192;
    float2 a0 = __half22float2(p[0]);
    float2 a1 = __half22float2(p[192]);
    float2 a2 = __half22float2(p[rs]);
    float2 a3 = __half22float2(p[rs + 192]);
    ((__half2*)out)[idx] = __floats2half2_rn(0.25f * (a0.x + a1.x + a2.x + a3.x),
                                             0.25f * (a0.y + a1.y + a2.y + a3.y));
}

// ---------------- MHA v2: warp per query-PAIR; lane-per-key scores; fp16 K/V ----------
__global__ void mha_kernel(const float* __restrict__ q, const __half* __restrict__ qh, int qs,
                           const __half* __restrict__ kh, int ks,
                           const __half* __restrict__ vh, int vs,
                           float* __restrict__ of, __half* __restrict__ oh, int os,
                           int Nq, int Nk, const __half* __restrict__ addsrc)
{
    extern __shared__ float sm[];
    float2* ksh2 = (float2*)sm;
    float2* vsh2 = ksh2 + (size_t)Nk * 32;
    const int nw = blockDim.x >> 5;
    float2* qbase = vsh2 + (size_t)Nk * 32;
    float*  scbase = (float*)(qbase + nw * 64);

    const int bh = blockIdx.x;
    const int b = bh / 6, h = bh % 6;
    const int tid = threadIdx.x;
    const int warp = tid >> 5, lane = tid & 31;

    const __half* kb = kh + (size_t)b * Nk * ks + h * 64;
    const __half* vb = vh + (size_t)b * Nk * vs + h * 64;
    for (int idx = tid; idx < Nk * 32; idx += blockDim.x) {
        int j = idx >> 5, d2 = idx & 31;
        ksh2[idx] = __half22float2(*(const __half2*)(kb + (size_t)j * ks + 2 * d2));
        vsh2[idx] = __half22float2(*(const __half2*)(vb + (size_t)j * vs + 2 * d2));
    }
    __syncthreads();

    float2* qa2 = qbase + warp * 64;
    float2* qb2 = qa2 + 32;
    float* sca = scbase + warp * 2 * Nk;
    float* scb = sca + Nk;

    const int npairs = (Nq + 1) >> 1;
    for (int qp = blockIdx.y * nw + warp; qp < npairs; qp += gridDim.y * nw) {
        const int qia = 2 * qp;
        const int qib = qia + 1;
        const bool hasb = qib < Nq;
        const int qibc = hasb ? qib : qia;
        {
            float a0, a1, b0, b1;
            if (qh) {
                __half2 ha = *(const __half2*)(qh + ((size_t)b * Nq + qia) * qs + h * 64 + 2 * lane);
                __half2 hb = *(const __half2*)(qh + ((size_t)b * Nq + qibc) * qs + h * 64 + 2 * lane);
                float2 fa = __half22float2(ha), fb = __half22float2(hb);
                a0 = fa.x; a1 = fa.y; b0 = fb.x; b1 = fb.y;
            } else {
                float2 fa = *(const float2*)(q + ((size_t)b * Nq + qia) * qs + h * 64 + 2 * lane);
                float2 fb = *(const float2*)(q + ((size_t)b * Nq + qibc) * qs + h * 64 + 2 * lane);
                a0 = fa.x; a1 = fa.y; b0 = fb.x; b1 = fb.y;
            }
            qa2[lane] = make_float2(a0 * 0.125f, a1 * 0.125f);
            qb2[lane] = make_float2(b0 * 0.125f, b1 * 0.125f);
        }
        __syncwarp();

        float ma = -1e30f, mb = -1e30f;
        for (int j0 = 0; j0 < Nk; j0 += 32) {
            const int j = j0 + lane;
            const float2* kj = ksh2 + (size_t)j * 32;
            float sa0 = 0.f, sa1 = 0.f, sb0 = 0.f, sb1 = 0.f;
            int d2 = lane;
            #pragma unroll 8
            for (int dd = 0; dd < 32; dd += 2) {
                float2 k2 = kj[d2];
                float2 qa = qa2[d2];
                float2 qb = qb2[d2];
                sa0 = fmaf(k2.x, qa.x, fmaf(k2.y, qa.y, sa0));
                sb0 = fmaf(k2.x, qb.x, fmaf(k2.y, qb.y, sb0));
                int d2b = (d2 + 1) & 31;
                float2 k3 = kj[d2b];
                float2 qa3 = qa2[d2b];
                float2 qb3 = qb2[d2b];
                sa1 = fmaf(k3.x, qa3.x, fmaf(k3.y, qa3.y, sa1));
                sb1 = fmaf(k3.x, qb3.x, fmaf(k3.y, qb3.y, sb1));
                d2 = (d2 + 2) & 31;
            }
            float sa = sa0 + sa1, sb = sb0 + sb1;
            if (j < Nk) {
                sca[j] = sa; scb[j] = sb;
                ma = fmaxf(ma, sa); mb = fmaxf(mb, sb);
            }
        }
        #pragma unroll
        for (int off = 16; off; off >>= 1) {
            ma = fmaxf(ma, __shfl_xor_sync(0xffffffffu, ma, off));
            mb = fmaxf(mb, __shfl_xor_sync(0xffffffffu, mb, off));
        }
        float suma = 0.f, sumb = 0.f;
        for (int j = lane; j < Nk; j += 32) {
            float ea = expf(sca[j] - ma); sca[j] = ea; suma += ea;
            float eb = expf(scb[j] - mb); scb[j] = eb; sumb += eb;
        }
        #pragma unroll
        for (int off = 16; off; off >>= 1) {
            suma += __shfl_xor_sync(0xffffffffu, suma, off);
            sumb += __shfl_xor_sync(0xffffffffu, sumb, off);
        }
        const float inva = 1.f / suma, invb = 1.f / sumb;
        __syncwarp();

        float2 oa = make_float2(0.f, 0.f), ob = make_float2(0.f, 0.f);
        const float2* vrow = vsh2 + lane;
        for (int j = 0; j < Nk; j++) {
            float pa = sca[j], pb = scb[j];
            float2 v2 = vrow[(size_t)j * 32];
            oa.x = fmaf(pa, v2.x, oa.x); oa.y = fmaf(pa, v2.y, oa.y);
            ob.x = fmaf(pb, v2.x, ob.x); ob.y = fmaf(pb, v2.y, ob.y);
        }
        oa.x *= inva; oa.y *= inva; ob.x *= invb; ob.y *= invb;
        if (addsrc) {
            float2 ra = __half22float2(*(const __half2*)(addsrc + ((size_t)b * Nq + qia) * 384 + h * 64 + 2 * lane));
            oa.x += ra.x; oa.y += ra.y;
            if (hasb) {
                float2 rb = __half22float2(*(const __half2*)(addsrc + ((size_t)b * Nq + qib) * 384 + h * 64 + 2 * lane));
                ob.x += rb.x; ob.y += rb.y;
            }
        }
        const size_t oba = ((size_t)b * Nq + qia) * os + h * 64 + 2 * lane;
        if (of) {
            *(float2*)&of[oba] = oa;
            if (hasb) *(float2*)&of[oba + os] = ob;
        }
        if (oh) {
            *(__half2*)&oh[oba] = __floats2half2_rn(oa.x, oa.y);
            if (hasb) *(__half2*)&oh[oba + os] = __floats2half2_rn(ob.x, ob.y);
        }
        __syncwarp();
    }
}

// ---------------- launch ----------------
extern "C" void kernel_launch(void* const* d_in, const int* in_sizes, int n_in,
                              void* d_out, int out_size)
{
    const float* x        = (const float*)d_in[0];
    const float* gtok     = (const float*)d_in[1];
    const float* we_dw_w  = (const float*)d_in[2];
    const float* we_dw_b  = (const float*)d_in[3];
    const float* we_ln_g  = (const float*)d_in[4];
    const float* we_ln_b  = (const float*)d_in[5];
    const float* we_pw1_w = (const float*)d_in[6];
    const float* we_pw1_b = (const float*)d_in[7];
    const float* we_pw2_w = (const float*)d_in[8];
    const float* we_pw2_b = (const float*)d_in[9];
    const float* we_gamma = (const float*)d_in[10];
    const float* cb_conv_w= (const float*)d_in[11];
    const float* cb_ln_g  = (const float*)d_in[12];
    const float* cb_ln_b  = (const float*)d_in[13];
    const float* ga_qkv_w = (const float*)d_in[14];
    const float* ug_kv_w  = (const float*)d_in[15];
    const float* ug_q_w   = (const float*)d_in[16];
    const float* gb_kv_w  = (const float*)d_in[17];
    const float* gb_q_w   = (const float*)d_in[18];
    const float* proj_w   = (const float*)d_in[19];
    const float* proj_b   = (const float*)d_in[20];

    float* out = (float*)d_out;
    float* gt_out = out + GT_OFF;

    __half *ln1h, *h1h, *pool1h, *xdh, *xdsh, *gtokh, *gth, *xh, *qxh, *xsumh;
    __half *qkvh, *kv2h, *kv3h;
    __half *pw1T, *pw2T, *qkvT, *ugkvT, *ugqT, *gbkvT, *gbqT, *projT, *convT;
    float *c2pre, *qg;
    cudaGetSymbolAddress((void**)&ln1h,   h_ln1);
    cudaGetSymbolAddress((void**)&h1h,    h_h1);
    cudaGetSymbolAddress((void**)&pool1h, h_pool1);
    cudaGetSymbolAddress((void**)&xdh,    h_xd);
    cudaGetSymbolAddress((void**)&xdsh,   h_xds);
    cudaGetSymbolAddress((void**)&gtokh,  h_gtok);
    cudaGetSymbolAddress((void**)&gth,    h_gt);
    cudaGetSymbolAddress((void**)&xh,     h_x);
    cudaGetSymbolAddress((void**)&qxh,    h_qx);
    cudaGetSymbolAddress((void**)&xsumh,  h_xsum);
    cudaGetSymbolAddress((void**)&qkvh,   h_qkv);
    cudaGetSymbolAddress((void**)&kv2h,   h_kv2);
    cudaGetSymbolAddress((void**)&kv3h,   h_kv3);
    cudaGetSymbolAddress((void**)&c2pre,  g_c2pre);
    cudaGetSymbolAddress((void**)&qg,     g_qg);
    cudaGetSymbolAddress((void**)&pw1T,   w_pw1T);
    cudaGetSymbolAddress((void**)&pw2T,   w_pw2T);
    cudaGetSymbolAddress((void**)&qkvT,   w_qkvT);
    cudaGetSymbolAddress((void**)&ugkvT,  w_ugkvT);
    cudaGetSymbolAddress((void**)&ugqT,   w_ugqT);
    cudaGetSymbolAddress((void**)&gbkvT,  w_gbkvT);
    cudaGetSymbolAddress((void**)&gbqT,   w_gbqT);
    cudaGetSymbolAddress((void**)&projT,  w_projT);
    cudaGetSymbolAddress((void**)&convT,  w_convT);
    __half* xlocalh = ln1h;   // reuse: ln1h is dead after MLP1

    const int SMEM_TG  = 61440;
    const int SMEM196 = 2 * 196 * 256 + 4 * (512 + 8 * 196);   // 108672
    const int SMEM49  = 2 * 49  * 256 + 4 * (512 + 8 * 49);    // 28704
    cudaFuncSetAttribute(mha_kernel, cudaFuncAttributeMaxDynamicSharedMemorySize, SMEM196);
    cudaFuncSetAttribute((hgemm<0,0>), cudaFuncAttributeMaxDynamicSharedMemorySize, SMEM_TG);
    cudaFuncSetAttribute((hgemm<1,0>), cudaFuncAttributeMaxDynamicSharedMemorySize, SMEM_TG);
    cudaFuncSetAttribute((hgemm<2,0>), cudaFuncAttributeMaxDynamicSharedMemorySize, SMEM_TG);
    cudaFuncSetAttribute((hgemm<3,0>), cudaFuncAttributeMaxDynamicSharedMemorySize, SMEM_TG);
    cudaFuncSetAttribute((hgemm<0,1>), cudaFuncAttributeMaxDynamicSharedMemorySize, SMEM_TG);

    // second stream + events for overlap (host objects; graph-capture legal fork/join)
    cudaStream_t s2;
    cudaStreamCreateWithFlags(&s2, cudaStreamNonBlocking);
    cudaEvent_t evFork, evJoin;
    cudaEventCreateWithFlags(&evFork, cudaEventDisableTiming);
    cudaEventCreateWithFlags(&evJoin, cudaEventDisableTiming);

    // ---- fused weight prep (one launch) ----
    prep_weights_kernel<<<(PREP_TOTAL + 255) / 256, 256>>>(
        we_pw1_w, we_pw2_w, ga_qkv_w, ug_kv_w, ug_q_w, gb_kv_w, gb_q_w, proj_w,
        cb_conv_w, gtok,
        pw1T, pw2T, qkvT, ugkvT, ugqT, gbkvT, gbqT, projT, convT, gtokh);

    // ConvEncoder: dwconv + LN -> fp16 (also emits x fp16)
    dwconv_ln_kernel<<<50176, 128>>>(x, we_dw_w, we_dw_b, we_ln_g, we_ln_b, ln1h, xh);

    // ---- fork: qx GEMM + qg GEMM on s2 (depend only on prep + dwconv outputs) ----
    cudaEventRecord(evFork, 0);
    cudaStreamWaitEvent(s2, evFork, 0);
    hgemm<0,0><<<dim3(3, 392), 256, SMEM_TG, s2>>>(xh, gbqT, nullptr, nullptr, nullptr,
                                                   nullptr, qxh, 50176, 384, 384);
    hgemm<0,0><<<dim3(3, 7), 256, SMEM_TG, s2>>>(gtokh, ugqT, nullptr, nullptr, nullptr,
                                                 qg, nullptr, 784, 384, 384);
    cudaEventRecord(evJoin, s2);

    // MLP1: gelu(ln1 @ pw1 + b1) -> fp16 hidden
    hgemm<2,0><<<dim3(12, 392), 256, SMEM_TG>>>(ln1h, pw1T, we_pw1_b, nullptr, nullptr,
                                                nullptr, h1h, 50176, 1536, 384);
    // MLP2 + layer-scale + residual -> fp16 xlocal (reuses ln1h)
    hgemm<3,0><<<dim3(3, 392), 256, SMEM_TG>>>(h1h, pw2T, we_pw2_b, we_gamma, x,
                                               nullptr, xlocalh, 50176, 384, 1536);
    // down_1: 56->28 fp16->fp16
    avgpool2h_kernel<<<(2408448 + 255) / 256, 256>>>(xlocalh, pool1h, 16, 28, 28);

    // ConvBNReLU: implicit-GEMM conv (no im2col), then fused LN+ReLU+pool -> fp16 tokens
    hgemm<0,1><<<dim3(3, 98), 256, SMEM_TG>>>(pool1h, convT, nullptr, nullptr, nullptr,
                                              c2pre, nullptr, 12544, 384, 3456);
    ln_relu_pool_kernel<<<3136, 128>>>(c2pre, cb_ln_g, cb_ln_b, xdh);

    // global aggregation MHSA (qkv fp16)
    hgemm<0,0><<<dim3(9, 25), 256, SMEM_TG>>>(xdh, qkvT, nullptr, nullptr, nullptr,
                                              nullptr, qkvh, 3136, 1152, 384);
    mha_kernel<<<dim3(96, 8), 128, SMEM196>>>(nullptr, qkvh, 1152, qkvh + 384, 1152,
                                              qkvh + 768, 1152,
                                              nullptr, xdsh, 384, 196, 196, nullptr);

    // global token update (kv2 fp16)
    hgemm<0,0><<<dim3(6, 25), 256, SMEM_TG>>>(xdsh, ugkvT, nullptr, nullptr, nullptr,
                                              nullptr, kv2h, 3136, 768, 384);
    // ---- join: qg (and qx) ready ----
    cudaStreamWaitEvent(0, evJoin, 0);
    mha_kernel<<<dim3(96, 2), 128, SMEM196>>>(qg, nullptr, 384, kv2h, 768, kv2h + 384, 768,
                                              gt_out, gth, 384, 49, 196, nullptr);

    // global broadcast (kv3 fp16)
    hgemm<0,0><<<dim3(6, 7), 256, SMEM_TG>>>(gth, gbkvT, nullptr, nullptr, nullptr,
                                             nullptr, kv3h, 784, 768, 384);
    // x_global + x_local(fp16) fused into MHA output -> fp16 xsum
    mha_kernel<<<dim3(96, 64), 128, SMEM49>>>(nullptr, qxh, 384, kv3h, 768, kv3h + 384, 768,
                                              nullptr, xsumh, 384, 3136, 49, xlocalh);

    // final projection: xsum @ proj_w + proj_b -> out
    hgemm<1,0><<<dim3(3, 392), 256, SMEM_TG>>>(xsumh, projT, proj_b, nullptr, nullptr,
                                               out, nullptr, 50176, 384, 384);
}

// round 17
// speedup vs baseline: 1.2118x; 1.0021x over previous
#include <cuda_runtime.h>
#include <cuda_fp16.h>
#include <math.h>
#include <stdint.h>

// ---------------- constants ----------------
#define GT_OFF 19267584      // 16*3136*384

// ---------------- scratch (device globals; allocation-free) ----------------
__device__ __half h_ln1[19267584];     // dwconv+LN out; later reused as xlocal fp16
__device__ __half h_h1[77070336];      // MLP hidden
__device__ __half h_pool1[4816896];    // down_1 fp16 (implicit-conv A operand)
__device__ __half h_xd[1204224];       // downsampled tokens
__device__ __half h_xds[1204224];      // global-agg MHA out
__device__ __half h_gtok[301056];      // global_token fp16
__device__ __half h_gt[301056];        // updated global token fp16
__device__ __half h_x[19267584];       // x fp16
__device__ __half h_qx[19267584];      // q for global broadcast (fp16)
__device__ __half h_xsum[19267584];    // xlocal + xglobal
__device__ __half h_qkv[3612672];      // [B,196,1152] fp16
__device__ __half h_kv2[2408448];      // [B,196,768] fp16
__device__ __half h_kv3[602112];       // [B,49,768] fp16
__device__ float g_c2pre[4816896];     // conv2 pre-LN
__device__ float g_qg[301056];         // [B,49,384]
__device__ __half w_pw1T[589824];
__device__ __half w_pw2T[589824];
__device__ __half w_qkvT[442368];
__device__ __half w_ugkvT[294912];
__device__ __half w_ugqT[147456];
__device__ __half w_gbkvT[294912];
__device__ __half w_gbqT[147456];
__device__ __half w_projT[147456];
__device__ __half w_convT[1327104];

// ---------------- helpers ----------------
__device__ __forceinline__ float gelu_exact(float x){
    return 0.5f * x * (1.0f + erff(x * 0.70710678118654752f));
}
__device__ __forceinline__ uint32_t smem_u32(const void* p) {
    uint32_t a;
    asm("{ .reg .u64 t; cvta.to.shared.u64 t, %1; cvt.u32.u64 %0, t; }" : "=r"(a) : "l"(p));
    return a;
}
__device__ __forceinline__ void mma16(float* d, const unsigned* a, const unsigned* b){
    asm volatile("mma.sync.aligned.m16n8k16.row.col.f32.f16.f16.f32 "
        "{%0,%1,%2,%3},{%4,%5,%6,%7},{%8,%9},{%0,%1,%2,%3};"
        : "+f"(d[0]), "+f"(d[1]), "+f"(d[2]), "+f"(d[3])
        : "r"(a[0]), "r"(a[1]), "r"(a[2]), "r"(a[3]), "r"(b[0]), "r"(b[1]));
}
__device__ __forceinline__ void ldsm4(unsigned& r0, unsigned& r1, unsigned& r2, unsigned& r3,
                                      uint32_t addr){
    asm volatile("ldmatrix.sync.aligned.m8n8.x4.shared.b16 {%0,%1,%2,%3}, [%4];"
        : "=r"(r0), "=r"(r1), "=r"(r2), "=r"(r3) : "r"(addr));
}
__device__ __forceinline__ void cp16(uint32_t s, const void* g) {
    asm volatile("cp.async.cg.shared.global [%0], [%1], 16;" :: "r"(s), "l"(g));
}
__device__ __forceinline__ void cp16z(uint32_t s, const void* g, int sz) {
    asm volatile("cp.async.cg.shared.global [%0], [%1], 16, %2;" :: "r"(s), "l"(g), "r"(sz));
}
#define CP_COMMIT() asm volatile("cp.async.commit_group;" ::: "memory")
#define CP_WAIT(n)  asm volatile("cp.async.wait_group %0;" :: "n"(n) : "memory")

// A-operand staging: dense (CONV=0) or implicit 3x3 SAME conv over [16,28,28,384] (CONV=1)
template<int CONV>
__device__ __forceinline__ void stageA(uint32_t dst, const __half* __restrict__ Abase,
                                       int K, int r, int c, int ko, bool rowok,
                                       int b, int h, int w)
{
    if (!CONV) {
        if (rowok) cp16(dst, Abase + (size_t)r * K + ko + c * 8);
    } else {
        int k = ko + c * 8;
        int kk = k / 384;            // tap index 0..8
        int cin = k - kk * 384;      // channel (8-aligned)
        int ky = kk / 3, kx = kk - 3 * ky;
        int hh = h + ky - 1, ww = w + kx - 1;
        bool inb = ((unsigned)hh < 28u) && ((unsigned)ww < 28u);
        const __half* src = inb
            ? Abase + (((size_t)(b * 28 + hh) * 28 + ww) * 384 + cin)
            : Abase;
        cp16z(dst, src, inb ? 16 : 0);
    }
}

// ---------------- FP16 GEMM: mma.m16n8k16 + ldmatrix + cp.async 3-stage ring (K32) -------
// CTA tile 128x128, 256 threads (8 warps x 64x32). smem 3 x (A 128x40h + B 128x40h) = 61440 B.
// MODE 0: C = A@B ; 1: +bias ; 2: gelu(+bias) ; 3: (+bias)*gamma + res
template<int MODE, int CONV>
__global__ void __launch_bounds__(256, 2) hgemm(
    const __half* __restrict__ A, const __half* __restrict__ BT,
    const float* __restrict__ bias, const float* __restrict__ gamma,
    const float* __restrict__ res,
    float* __restrict__ Cf, __half* __restrict__ Ch,
    int M, int N, int K)
{
    extern __shared__ __half smh[];
    __half* Asm = smh;              // [3][128][40]
    __half* Bsm = smh + 3 * 5120;   // [3][128][40]
    const uint32_t AsmU = smem_u32(Asm);
    const uint32_t BsmU = smem_u32(Bsm);

    const int tid  = threadIdx.x;
    const int warp = tid >> 5, lane = tid & 31;
    const int wm = (warp >> 2) * 64;
    const int wn = (warp & 3) * 32;
    const int bm = blockIdx.y * 128;
    const int bn = blockIdx.x * 128;

    float acc[4][4][4];
    #pragma unroll
    for (int t = 0; t < 4; t++)
        #pragma unroll
        for (int u = 0; u < 4; u++)
            #pragma unroll
            for (int e = 0; e < 4; e++) acc[t][u][e] = 0.f;

    const int maxrowA = M - bm;
    const __half* Abase = CONV ? A : (A + (size_t)bm * K);
    const __half* Bbase = BT + (size_t)bn * K;

    const int cid0 = tid * 2;
    const int r0 = cid0 >> 2,       c0 = (cid0 & 3);
    const int r1 = (cid0 + 1) >> 2, c1 = ((cid0 + 1) & 3);
    const bool ok0 = r0 < maxrowA, ok1 = r1 < maxrowA;
    int b0 = 0, h0 = 0, w0 = 0, b1 = 0, h1 = 0, w1 = 0;
    if (CONV) {
        int p0 = bm + r0; b0 = p0 / 784; int q0 = p0 - b0 * 784; h0 = q0 / 28; w0 = q0 - h0 * 28;
        int p1 = bm + r1; b1 = p1 / 784; int q1 = p1 - b1 * 784; h1 = q1 / 28; w1 = q1 - h1 * 28;
    }

    const int a_row = lane & 15;
    const int a_kc  = (lane >> 4) & 1;
    const int b_row = (lane & 7) | ((lane >> 1) & 8);
    const int b_kc  = (lane >> 3) & 1;

    const int T = K >> 5;

    // prologue
    {
        stageA<CONV>(AsmU + r0 * 80 + c0 * 16, Abase, K, r0, c0, 0, ok0, b0, h0, w0);
        stageA<CONV>(AsmU + r1 * 80 + c1 * 16, Abase, K, r1, c1, 0, ok1, b1, h1, w1);
        cp16(BsmU + r0 * 80 + c0 * 16, Bbase + (size_t)r0 * K + c0 * 8);
        cp16(BsmU + r1 * 80 + c1 * 16, Bbase + (size_t)r1 * K + c1 * 8);
        CP_COMMIT();
        if (T > 1) {
            stageA<CONV>(AsmU + 10240 + r0 * 80 + c0 * 16, Abase, K, r0, c0, 32, ok0, b0, h0, w0);
            stageA<CONV>(AsmU + 10240 + r1 * 80 + c1 * 16, Abase, K, r1, c1, 32, ok1, b1, h1, w1);
            cp16(BsmU + 10240 + r0 * 80 + c0 * 16, Bbase + (size_t)r0 * K + 32 + c0 * 8);
            cp16(BsmU + 10240 + r1 * 80 + c1 * 16, Bbase + (size_t)r1 * K + 32 + c1 * 8);
            CP_COMMIT();
        }
    }

    int buf = 0, nbuf = (T > 2) ? 2 : (T == 2 ? 0 : 1);
    for (int it = 0; it < T; ++it) {
        if (it + 1 < T) CP_WAIT(1); else CP_WAIT(0);
        __syncthreads();
        if (it + 2 < T) {
            const int ko = (it + 2) << 5;
            const uint32_t off = (uint32_t)nbuf * 10240;
            stageA<CONV>(AsmU + off + r0 * 80 + c0 * 16, Abase, K, r0, c0, ko, ok0, b0, h0, w0);
            stageA<CONV>(AsmU + off + r1 * 80 + c1 * 16, Abase, K, r1, c1, ko, ok1, b1, h1, w1);
            cp16(BsmU + off + r0 * 80 + c0 * 16, Bbase + (size_t)r0 * K + ko + c0 * 8);
            cp16(BsmU + off + r1 * 80 + c1 * 16, Bbase + (size_t)r1 * K + ko + c1 * 8);
            CP_COMMIT();
        }
        const uint32_t Abuf = AsmU + (uint32_t)buf * 10240;
        const uint32_t Bbuf = BsmU + (uint32_t)buf * 10240;
        #pragma unroll
        for (int ks = 0; ks < 2; ks++) {
            unsigned af[4][4], bf[4][2];
            #pragma unroll
            for (int t = 0; t < 4; t++) {
                const uint32_t addr = Abuf + (uint32_t)(wm + t * 16 + a_row) * 80
                                    + (uint32_t)(ks * 16 + a_kc * 8) * 2;
                ldsm4(af[t][0], af[t][1], af[t][2], af[t][3], addr);
            }
            #pragma unroll
            for (int u2 = 0; u2 < 2; u2++) {
                const uint32_t addr = Bbuf + (uint32_t)(wn + u2 * 16 + b_row) * 80
                                    + (uint32_t)(ks * 16 + b_kc * 8) * 2;
                ldsm4(bf[2 * u2][0], bf[2 * u2][1], bf[2 * u2 + 1][0], bf[2 * u2 + 1][1], addr);
            }
            #pragma unroll
            for (int t = 0; t < 4; t++)
                #pragma unroll
                for (int u = 0; u < 4; u++)
                    mma16(acc[t][u], af[t], bf[u]);
        }
        buf = (buf == 2) ? 0 : buf + 1;
        nbuf = (nbuf == 2) ? 0 : nbuf + 1;
    }

    // ---- epilogue ----
    #pragma unroll
    for (int t = 0; t < 4; t++) {
        const int row0 = bm + wm + t * 16 + (lane >> 2);
        #pragma unroll
        for (int u = 0; u < 4; u++) {
            const int col = bn + wn + u * 8 + ((lane & 3) << 1);
            float b0f = 0.f, b1f = 0.f;
            if (MODE >= 1) { b0f = bias[col]; b1f = bias[col + 1]; }
            #pragma unroll
            for (int h = 0; h < 2; h++) {
                const int row = row0 + h * 8;
                if (row >= M) continue;
                float v0 = acc[t][u][h * 2 + 0] + b0f;
                float v1 = acc[t][u][h * 2 + 1] + b1f;
                if (MODE == 2) { v0 = gelu_exact(v0); v1 = gelu_exact(v1); }
                if (MODE == 3) {
                    const float* rr = res + (size_t)row * N + col;
                    v0 = v0 * gamma[col]     + rr[0];
                    v1 = v1 * gamma[col + 1] + rr[1];
                }
                if (Cf) *(float2*)&Cf[(size_t)row * N + col] = make_float2(v0, v1);
                if (Ch) *(__half2*)&Ch[(size_t)row * N + col] = __floats2half2_rn(v0, v1);
            }
        }
    }
}

// ---------------- fused weight prep: all transposes + f2h in ONE kernel ----------------
__global__ void prep_weights_kernel(
    const float* __restrict__ pw1, const float* __restrict__ pw2,
    const float* __restrict__ qkv, const float* __restrict__ ugkv,
    const float* __restrict__ ugq, const float* __restrict__ gbkv,
    const float* __restrict__ gbq, const float* __restrict__ proj,
    const float* __restrict__ convw, const float* __restrict__ gtok,
    __half* __restrict__ pw1T, __half* __restrict__ pw2T,
    __half* __restrict__ qkvT, __half* __restrict__ ugkvT,
    __half* __restrict__ ugqT, __half* __restrict__ gbkvT,
    __half* __restrict__ gbqT, __half* __restrict__ projT,
    __half* __restrict__ convT, __half* __restrict__ gtokh)
{
    int idx = blockIdx.x * blockDim.x + threadIdx.x;
    if (idx < 589824) {
        int n = idx / 384, k = idx % 384;
        pw1T[idx] = __float2half(pw1[(size_t)k * 1536 + n]); return;
    }
    idx -= 589824;
    if (idx < 589824) {
        int n = idx / 1536, k = idx % 1536;
        pw2T[idx] = __float2half(pw2[(size_t)k * 384 + n]); return;
    }
    idx -= 589824;
    if (idx < 442368) {
        int n = idx / 384, k = idx % 384;
        qkvT[idx] = __float2half(qkv[(size_t)k * 1152 + n]); return;
    }
    idx -= 442368;
    if (idx < 294912) {
        int n = idx / 384, k = idx % 384;
        ugkvT[idx] = __float2half(ugkv[(size_t)k * 768 + n]); return;
    }
    idx -= 294912;
    if (idx < 147456) {
        int n = idx / 384, k = idx % 384;
        ugqT[idx] = __float2half(ugq[(size_t)k * 384 + n]); return;
    }
    idx -= 147456;
    if (idx < 294912) {
        int n = idx / 384, k = idx % 384;
        gbkvT[idx] = __float2half(gbkv[(size_t)k * 768 + n]); return;
    }
    idx -= 294912;
    if (idx < 147456) {
        int n = idx / 384, k = idx % 384;
        gbqT[idx] = __float2half(gbq[(size_t)k * 384 + n]); return;
    }
    idx -= 147456;
    if (idx < 147456) {
        int n = idx / 384, k = idx % 384;
        projT[idx] = __float2half(proj[(size_t)k * 384 + n]); return;
    }
    idx -= 147456;
    if (idx < 1327104) {
        int o = idx / 3456, j = idx % 3456;
        int kk = j / 384, i = j % 384;
        convT[idx] = __float2half(convw[(size_t)o * 3456 + i * 9 + kk]); return;
    }
    idx -= 1327104;
    if (idx < 301056) {
        gtokh[idx] = __float2half(gtok[idx]);
    }
}
#define PREP_TOTAL 4282368

// ---------------- dwconv 3x3 depthwise + LN(1e-6) -> fp16; also emits x as fp16 ----------
__global__ void dwconv_ln_kernel(const float* __restrict__ x,
                                 const float* __restrict__ dw, const float* __restrict__ db,
                                 const float* __restrict__ gam, const float* __restrict__ bet,
                                 __half* __restrict__ out, __half* __restrict__ xh)
{
    __shared__ float sred[64];
    const int pix = blockIdx.x;
    const int b = pix / 3136, hw = pix % 3136;
    const int h = hw / 56, w = hw % 56;
    const int tid = threadIdx.x;
    float v[3];
    float s = 0.f, s2 = 0.f;
    #pragma unroll
    for (int r = 0; r < 3; r++) {
        int c = tid + r * 128;
        float acc = db[c];
        float ctr = 0.f;
        #pragma unroll
        for (int ky = 0; ky < 3; ky++) {
            int hh = h + ky - 1;
            if ((unsigned)hh >= 56u) continue;
            #pragma unroll
            for (int kx = 0; kx < 3; kx++) {
                int ww = w + kx - 1;
                if ((unsigned)ww >= 56u) continue;
                float xv = x[((size_t)b * 3136 + hh * 56 + ww) * 384 + c];
                if (ky == 1 && kx == 1) ctr = xv;
                acc = fmaf(xv, dw[c * 9 + ky * 3 + kx], acc);
            }
        }
        xh[(size_t)pix * 384 + c] = __float2half(ctr);
        v[r] = acc; s += acc; s2 = fmaf(acc, acc, s2);
    }
    int lane = tid & 31, warp = tid >> 5;
    #pragma unroll
    for (int off = 16; off; off >>= 1) {
        s  += __shfl_xor_sync(0xffffffffu, s, off);
        s2 += __shfl_xor_sync(0xffffffffu, s2, off);
    }
    if (lane == 0) { sred[warp] = s; sred[warp + 32] = s2; }
    __syncthreads();
    if (warp == 0) {
        float a  = (lane < 4) ? sred[lane] : 0.f;
        float b2 = (lane < 4) ? sred[lane + 32] : 0.f;
        #pragma unroll
        for (int off = 2; off; off >>= 1) {
            a  += __shfl_xor_sync(0xffffffffu, a, off);
            b2 += __shfl_xor_sync(0xffffffffu, b2, off);
        }
        if (lane == 0) { sred[0] = a; sred[1] = b2; }
    }
    __syncthreads();
    float mean = sred[0] * (1.f / 384.f);
    float var  = sred[1] * (1.f / 384.f) - mean * mean;
    float rstd = rsqrtf(var + 1e-6f);
    #pragma unroll
    for (int r = 0; r < 3; r++) {
        int c = tid + r * 128;
        out[(size_t)pix * 384 + c] = __float2half((v[r] - mean) * rstd * gam[c] + bet[c]);
    }
}

// ---------------- fused LN(1e-5)+ReLU+AvgPool2(2,2): [16,28,28,384]f32 -> [16,14,14,384]f16
__global__ void ln_relu_pool_kernel(const float* __restrict__ in,
                                    const float* __restrict__ gam, const float* __restrict__ bet,
                                    __half* __restrict__ out)
{
    __shared__ float sred[4][4][2];
    const int opix = blockIdx.x;
    const int b = opix / 196, q = opix % 196;
    const int ho = q / 14, wo = q % 14;
    const int tid = threadIdx.x;
    const int lane = tid & 31, warp = tid >> 5;

    size_t ibase[4];
    #pragma unroll
    for (int pp = 0; pp < 4; pp++) {
        int hi = 2 * ho + (pp >> 1), wi = 2 * wo + (pp & 1);
        ibase[pp] = (((size_t)b * 28 + hi) * 28 + wi) * 384;
    }
    float v[4][3];
    float s[4] = {0.f, 0.f, 0.f, 0.f}, s2[4] = {0.f, 0.f, 0.f, 0.f};
    #pragma unroll
    for (int pp = 0; pp < 4; pp++) {
        #pragma unroll
        for (int r = 0; r < 3; r++) {
            float a = in[ibase[pp] + tid + r * 128];
            v[pp][r] = a; s[pp] += a; s2[pp] = fmaf(a, a, s2[pp]);
        }
    }
    #pragma unroll
    for (int pp = 0; pp < 4; pp++) {
        float a = s[pp], c = s2[pp];
        #pragma unroll
        for (int off = 16; off; off >>= 1) {
            a += __shfl_xor_sync(0xffffffffu, a, off);
            c += __shfl_xor_sync(0xffffffffu, c, off);
        }
        if (lane == 0) { sred[warp][pp][0] = a; sred[warp][pp][1] = c; }
    }
    __syncthreads();
    float mean[4], rstd[4];
    #pragma unroll
    for (int pp = 0; pp < 4; pp++) {
        float a = sred[0][pp][0] + sred[1][pp][0] + sred[2][pp][0] + sred[3][pp][0];
        float c = sred[0][pp][1] + sred[1][pp][1] + sred[2][pp][1] + sred[3][pp][1];
        float m = a * (1.f / 384.f);
        mean[pp] = m;
        rstd[pp] = rsqrtf(c * (1.f / 384.f) - m * m + 1e-5f);
    }
    #pragma unroll
    for (int r = 0; r < 3; r++) {
        int c = tid + r * 128;
        float g = gam[c], be = bet[c];
        float acc = 0.f;
        #pragma unroll
        for (int pp = 0; pp < 4; pp++) {
            float val = (v[pp][r] - mean[pp]) * rstd[pp] * g + be;
            acc += fmaxf(val, 0.f);
        }
        out[(size_t)opix * 384 + c] = __float2half(0.25f * acc);
    }
}

// ---------------- AvgPool2d(2,2) NHWC fp16 -> fp16 (half2-vectorized) ----------------
__global__ void avgpool2h_kernel(const __half* __restrict__ in, __half* __restrict__ out,
                                 int B_, int Ho, int Wo)
{
    int idx = blockIdx.x * blockDim.x + threadIdx.x;
    int total = B_ * Ho * Wo * 192;
    if (idx >= total) return;
    int c2 = idx % 192; int t = idx / 192;
    int wo = t % Wo; t /= Wo;
    int ho = t % Ho; int b = t / Ho;
    int Hi = Ho * 2, Wi = Wo * 2;
    const __half2* p = (const __half2*)(in + (((size_t)b * Hi + 2 * ho) * Wi + 2 * wo) * 384) + c2;
    const size_t rs = (size_t)Wi * 192;
    float2 a0 = __half22float2(p[0]);
    float2 a1 = __half22float2(p[192]);
    float2 a2 = __half22float2(p[rs]);
    float2 a3 = __half22float2(p[rs + 192]);
    ((__half2*)out)[idx] = __floats2half2_rn(0.25f * (a0.x + a1.x + a2.x + a3.x),
                                             0.25f * (a0.y + a1.y + a2.y + a3.y));
}

// ---------------- MHA v2: warp per query-PAIR; lane-per-key scores; fp16 K/V ----------
__global__ void mha_kernel(const float* __restrict__ q, const __half* __restrict__ qh, int qs,
                           const __half* __restrict__ kh, int ks,
                           const __half* __restrict__ vh, int vs,
                           float* __restrict__ of, __half* __restrict__ oh, int os,
                           int Nq, int Nk, const __half* __restrict__ addsrc)
{
    extern __shared__ float sm[];
    float2* ksh2 = (float2*)sm;
    float2* vsh2 = ksh2 + (size_t)Nk * 32;
    const int nw = blockDim.x >> 5;
    float2* qbase = vsh2 + (size_t)Nk * 32;
    float*  scbase = (float*)(qbase + nw * 64);

    const int bh = blockIdx.x;
    const int b = bh / 6, h = bh % 6;
    const int tid = threadIdx.x;
    const int warp = tid >> 5, lane = tid & 31;

    const __half* kb = kh + (size_t)b * Nk * ks + h * 64;
    const __half* vb = vh + (size_t)b * Nk * vs + h * 64;
    for (int idx = tid; idx < Nk * 32; idx += blockDim.x) {
        int j = idx >> 5, d2 = idx & 31;
        ksh2[idx] = __half22float2(*(const __half2*)(kb + (size_t)j * ks + 2 * d2));
        vsh2[idx] = __half22float2(*(const __half2*)(vb + (size_t)j * vs + 2 * d2));
    }
    __syncthreads();

    float2* qa2 = qbase + warp * 64;
    float2* qb2 = qa2 + 32;
    float* sca = scbase + warp * 2 * Nk;
    float* scb = sca + Nk;

    const int npairs = (Nq + 1) >> 1;
    for (int qp = blockIdx.y * nw + warp; qp < npairs; qp += gridDim.y * nw) {
        const int qia = 2 * qp;
        const int qib = qia + 1;
        const bool hasb = qib < Nq;
        const int qibc = hasb ? qib : qia;
        {
            float a0, a1, b0, b1;
            if (qh) {
                __half2 ha = *(const __half2*)(qh + ((size_t)b * Nq + qia) * qs + h * 64 + 2 * lane);
                __half2 hb = *(const __half2*)(qh + ((size_t)b * Nq + qibc) * qs + h * 64 + 2 * lane);
                float2 fa = __half22float2(ha), fb = __half22float2(hb);
                a0 = fa.x; a1 = fa.y; b0 = fb.x; b1 = fb.y;
            } else {
                float2 fa = *(const float2*)(q + ((size_t)b * Nq + qia) * qs + h * 64 + 2 * lane);
                float2 fb = *(const float2*)(q + ((size_t)b * Nq + qibc) * qs + h * 64 + 2 * lane);
                a0 = fa.x; a1 = fa.y; b0 = fb.x; b1 = fb.y;
            }
            qa2[lane] = make_float2(a0 * 0.125f, a1 * 0.125f);
            qb2[lane] = make_float2(b0 * 0.125f, b1 * 0.125f);
        }
        __syncwarp();

        float ma = -1e30f, mb = -1e30f;
        for (int j0 = 0; j0 < Nk; j0 += 32) {
            const int j = j0 + lane;
            const float2* kj = ksh2 + (size_t)j * 32;
            float sa0 = 0.f, sa1 = 0.f, sb0 = 0.f, sb1 = 0.f;
            int d2 = lane;
            #pragma unroll 8
            for (int dd = 0; dd < 32; dd += 2) {
                float2 k2 = kj[d2];
                float2 qa = qa2[d2];
                float2 qb = qb2[d2];
                sa0 = fmaf(k2.x, qa.x, fmaf(k2.y, qa.y, sa0));
                sb0 = fmaf(k2.x, qb.x, fmaf(k2.y, qb.y, sb0));
                int d2b = (d2 + 1) & 31;
                float2 k3 = kj[d2b];
                float2 qa3 = qa2[d2b];
                float2 qb3 = qb2[d2b];
                sa1 = fmaf(k3.x, qa3.x, fmaf(k3.y, qa3.y, sa1));
                sb1 = fmaf(k3.x, qb3.x, fmaf(k3.y, qb3.y, sb1));
                d2 = (d2 + 2) & 31;
            }
            float sa = sa0 + sa1, sb = sb0 + sb1;
            if (j < Nk) {
                sca[j] = sa; scb[j] = sb;
                ma = fmaxf(ma, sa); mb = fmaxf(mb, sb);
            }
        }
        #pragma unroll
        for (int off = 16; off; off >>= 1) {
            ma = fmaxf(ma, __shfl_xor_sync(0xffffffffu, ma, off));
            mb = fmaxf(mb, __shfl_xor_sync(0xffffffffu, mb, off));
        }
        float suma = 0.f, sumb = 0.f;
        for (int j = lane; j < Nk; j += 32) {
            float ea = expf(sca[j] - ma); sca[j] = ea; suma += ea;
            float eb = expf(scb[j] - mb); scb[j] = eb; sumb += eb;
        }
        #pragma unroll
        for (int off = 16; off; off >>= 1) {
            suma += __shfl_xor_sync(0xffffffffu, suma, off);
            sumb += __shfl_xor_sync(0xffffffffu, sumb, off);
        }
        const float inva = 1.f / suma, invb = 1.f / sumb;
        __syncwarp();

        float2 oa = make_float2(0.f, 0.f), ob = make_float2(0.f, 0.f);
        const float2* vrow = vsh2 + lane;
        for (int j = 0; j < Nk; j++) {
            float pa = sca[j], pb = scb[j];
            float2 v2 = vrow[(size_t)j * 32];
            oa.x = fmaf(pa, v2.x, oa.x); oa.y = fmaf(pa, v2.y, oa.y);
            ob.x = fmaf(pb, v2.x, ob.x); ob.y = fmaf(pb, v2.y, ob.y);
        }
        oa.x *= inva; oa.y *= inva; ob.x *= invb; ob.y *= invb;
        if (addsrc) {
            float2 ra = __half22float2(*(const __half2*)(addsrc + ((size_t)b * Nq + qia) * 384 + h * 64 + 2 * lane));
            oa.x += ra.x; oa.y += ra.y;
            if (hasb) {
                float2 rb = __half22float2(*(const __half2*)(addsrc + ((size_t)b * Nq + qib) * 384 + h * 64 + 2 * lane));
                ob.x += rb.x; ob.y += rb.y;
            }
        }
        const size_t oba = ((size_t)b * Nq + qia) * os + h * 64 + 2 * lane;
        if (of) {
            *(float2*)&of[oba] = oa;
            if (hasb) *(float2*)&of[oba + os] = ob;
        }
        if (oh) {
            *(__half2*)&oh[oba] = __floats2half2_rn(oa.x, oa.y);
            if (hasb) *(__half2*)&oh[oba + os] = __floats2half2_rn(ob.x, ob.y);
        }
        __syncwarp();
    }
}

// ---------------- launch ----------------
extern "C" void kernel_launch(void* const* d_in, const int* in_sizes, int n_in,
                              void* d_out, int out_size)
{
    const float* x        = (const float*)d_in[0];
    const float* gtok     = (const float*)d_in[1];
    const float* we_dw_w  = (const float*)d_in[2];
    const float* we_dw_b  = (const float*)d_in[3];
    const float* we_ln_g  = (const float*)d_in[4];
    const float* we_ln_b  = (const float*)d_in[5];
    const float* we_pw1_w = (const float*)d_in[6];
    const float* we_pw1_b = (const float*)d_in[7];
    const float* we_pw2_w = (const float*)d_in[8];
    const float* we_pw2_b = (const float*)d_in[9];
    const float* we_gamma = (const float*)d_in[10];
    const float* cb_conv_w= (const float*)d_in[11];
    const float* cb_ln_g  = (const float*)d_in[12];
    const float* cb_ln_b  = (const float*)d_in[13];
    const float* ga_qkv_w = (const float*)d_in[14];
    const float* ug_kv_w  = (const float*)d_in[15];
    const float* ug_q_w   = (const float*)d_in[16];
    const float* gb_kv_w  = (const float*)d_in[17];
    const float* gb_q_w   = (const float*)d_in[18];
    const float* proj_w   = (const float*)d_in[19];
    const float* proj_b   = (const float*)d_in[20];

    float* out = (float*)d_out;
    float* gt_out = out + GT_OFF;

    __half *ln1h, *h1h, *pool1h, *xdh, *xdsh, *gtokh, *gth, *xh, *qxh, *xsumh;
    __half *qkvh, *kv2h, *kv3h;
    __half *pw1T, *pw2T, *qkvT, *ugkvT, *ugqT, *gbkvT, *gbqT, *projT, *convT;
    float *c2pre, *qg;
    cudaGetSymbolAddress((void**)&ln1h,   h_ln1);
    cudaGetSymbolAddress((void**)&h1h,    h_h1);
    cudaGetSymbolAddress((void**)&pool1h, h_pool1);
    cudaGetSymbolAddress((void**)&xdh,    h_xd);
    cudaGetSymbolAddress((void**)&xdsh,   h_xds);
    cudaGetSymbolAddress((void**)&gtokh,  h_gtok);
    cudaGetSymbolAddress((void**)&gth,    h_gt);
    cudaGetSymbolAddress((void**)&xh,     h_x);
    cudaGetSymbolAddress((void**)&qxh,    h_qx);
    cudaGetSymbolAddress((void**)&xsumh,  h_xsum);
    cudaGetSymbolAddress((void**)&qkvh,   h_qkv);
    cudaGetSymbolAddress((void**)&kv2h,   h_kv2);
    cudaGetSymbolAddress((void**)&kv3h,   h_kv3);
    cudaGetSymbolAddress((void**)&c2pre,  g_c2pre);
    cudaGetSymbolAddress((void**)&qg,     g_qg);
    cudaGetSymbolAddress((void**)&pw1T,   w_pw1T);
    cudaGetSymbolAddress((void**)&pw2T,   w_pw2T);
    cudaGetSymbolAddress((void**)&qkvT,   w_qkvT);
    cudaGetSymbolAddress((void**)&ugkvT,  w_ugkvT);
    cudaGetSymbolAddress((void**)&ugqT,   w_ugqT);
    cudaGetSymbolAddress((void**)&gbkvT,  w_gbkvT);
    cudaGetSymbolAddress((void**)&gbqT,   w_gbqT);
    cudaGetSymbolAddress((void**)&projT,  w_projT);
    cudaGetSymbolAddress((void**)&convT,  w_convT);
    __half* xlocalh = ln1h;   // reuse: ln1h is dead after MLP1

    const int SMEM_TG  = 61440;
    const int SMEM196 = 2 * 196 * 256 + 4 * (512 + 8 * 196);   // 108672
    const int SMEM49  = 2 * 49  * 256 + 4 * (512 + 8 * 49);    // 28704
    cudaFuncSetAttribute(mha_kernel, cudaFuncAttributeMaxDynamicSharedMemorySize, SMEM196);
    cudaFuncSetAttribute((hgemm<0,0>), cudaFuncAttributeMaxDynamicSharedMemorySize, SMEM_TG);
    cudaFuncSetAttribute((hgemm<1,0>), cudaFuncAttributeMaxDynamicSharedMemorySize, SMEM_TG);
    cudaFuncSetAttribute((hgemm<2,0>), cudaFuncAttributeMaxDynamicSharedMemorySize, SMEM_TG);
    cudaFuncSetAttribute((hgemm<3,0>), cudaFuncAttributeMaxDynamicSharedMemorySize, SMEM_TG);
    cudaFuncSetAttribute((hgemm<0,1>), cudaFuncAttributeMaxDynamicSharedMemorySize, SMEM_TG);

    // second stream + events (host objects; graph-capture legal fork/join)
    cudaStream_t s2;
    cudaStreamCreateWithFlags(&s2, cudaStreamNonBlocking);
    cudaEvent_t evRoot, evPrep, evDw, evJoin;
    cudaEventCreateWithFlags(&evRoot, cudaEventDisableTiming);
    cudaEventCreateWithFlags(&evPrep, cudaEventDisableTiming);
    cudaEventCreateWithFlags(&evDw,   cudaEventDisableTiming);
    cudaEventCreateWithFlags(&evJoin, cudaEventDisableTiming);

    // ---- fork at root: prep on s2, dwconv on main (independent) ----
    cudaEventRecord(evRoot, 0);
    cudaStreamWaitEvent(s2, evRoot, 0);
    prep_weights_kernel<<<(PREP_TOTAL + 255) / 256, 256, 0, s2>>>(
        we_pw1_w, we_pw2_w, ga_qkv_w, ug_kv_w, ug_q_w, gb_kv_w, gb_q_w, proj_w,
        cb_conv_w, gtok,
        pw1T, pw2T, qkvT, ugkvT, ugqT, gbkvT, gbqT, projT, convT, gtokh);
    cudaEventRecord(evPrep, s2);

    // ConvEncoder: dwconv + LN -> fp16 (also emits x fp16)
    dwconv_ln_kernel<<<50176, 128>>>(x, we_dw_w, we_dw_b, we_ln_g, we_ln_b, ln1h, xh);
    cudaEventRecord(evDw, 0);

    // s2 continues: qx GEMM + qg GEMM (need prep [s2-ordered] + dwconv output)
    cudaStreamWaitEvent(s2, evDw, 0);
    hgemm<0,0><<<dim3(3, 392), 256, SMEM_TG, s2>>>(xh, gbqT, nullptr, nullptr, nullptr,
                                                   nullptr, qxh, 50176, 384, 384);
    hgemm<0,0><<<dim3(3, 7), 256, SMEM_TG, s2>>>(gtokh, ugqT, nullptr, nullptr, nullptr,
                                                 qg, nullptr, 784, 384, 384);
    cudaEventRecord(evJoin, s2);

    // main stream: wait for prep weights before MLP1
    cudaStreamWaitEvent(0, evPrep, 0);

    // MLP1: gelu(ln1 @ pw1 + b1) -> fp16 hidden
    hgemm<2,0><<<dim3(12, 392), 256, SMEM_TG>>>(ln1h, pw1T, we_pw1_b, nullptr, nullptr,
                                                nullptr, h1h, 50176, 1536, 384);
    // MLP2 + layer-scale + residual -> fp16 xlocal (reuses ln1h)
    hgemm<3,0><<<dim3(3, 392), 256, SMEM_TG>>>(h1h, pw2T, we_pw2_b, we_gamma, x,
                                               nullptr, xlocalh, 50176, 384, 1536);
    // down_1: 56->28 fp16->fp16
    avgpool2h_kernel<<<(2408448 + 255) / 256, 256>>>(xlocalh, pool1h, 16, 28, 28);

    // ConvBNReLU: implicit-GEMM conv (no im2col), then fused LN+ReLU+pool -> fp16 tokens
    hgemm<0,1><<<dim3(3, 98), 256, SMEM_TG>>>(pool1h, convT, nullptr, nullptr, nullptr,
                                              c2pre, nullptr, 12544, 384, 3456);
    ln_relu_pool_kernel<<<3136, 128>>>(c2pre, cb_ln_g, cb_ln_b, xdh);

    // global aggregation MHSA (qkv fp16)
    hgemm<0,0><<<dim3(9, 25), 256, SMEM_TG>>>(xdh, qkvT, nullptr, nullptr, nullptr,
                                              nullptr, qkvh, 3136, 1152, 384);
    mha_kernel<<<dim3(96, 8), 128, SMEM196>>>(nullptr, qkvh, 1152, qkvh + 384, 1152,
                                              qkvh + 768, 1152,
                                              nullptr, xdsh, 384, 196, 196, nullptr);

    // global token update (kv2 fp16)
    hgemm<0,0><<<dim3(6, 25), 256, SMEM_TG>>>(xdsh, ugkvT, nullptr, nullptr, nullptr,
                                              nullptr, kv2h, 3136, 768, 384);
    // ---- join: qg (and qx) ready ----
    cudaStreamWaitEvent(0, evJoin, 0);
    mha_kernel<<<dim3(96, 2), 128, SMEM196>>>(qg, nullptr, 384, kv2h, 768, kv2h + 384, 768,
                                              gt_out, gth, 384, 49, 196, nullptr);

    // global broadcast (kv3 fp16)
    hgemm<0,0><<<dim3(6, 7), 256, SMEM_TG>>>(gth, gbkvT, nullptr, nullptr, nullptr,
                                             nullptr, kv3h, 784, 768, 384);
    // x_global + x_local(fp16) fused into MHA output -> fp16 xsum
    mha_kernel<<<dim3(96, 64), 128, SMEM49>>>(nullptr, qxh, 384, kv3h, 768, kv3h + 384, 768,
                                              nullptr, xsumh, 384, 3136, 49, xlocalh);

    // final projection: xsum @ proj_w + proj_b -> out
    hgemm<1,0><<<dim3(3, 392), 256, SMEM_TG>>>(xsumh, projT, proj_b, nullptr, nullptr,
                                               out, nullptr, 50176, 384, 384);
}